// round 10
// baseline (speedup 1.0000x reference)
#include <cuda_runtime.h>
#include <cuda_bf16.h>
#include <stdint.h>
#include <math.h>

// Problem constants
#define B_   2
#define S_   4096
#define HID_ 1024
#define H_   16
#define D_   64
#define M_   (B_*S_)        // 8192
#define N1_  (3*H_*D_)      // 3072
#define N2_  HID_           // 1024
#define K3   3072           // split-K': [ah|al|ah] x [bh|bh|bl]

// ---------------------------------------------------------------------------
// Scratch (no cudaMalloc allowed)
// ---------------------------------------------------------------------------
__device__ __align__(256) __nv_bfloat16 g_A2[(size_t)M_*K3];      // 50.3 MB
__device__ __align__(256) __nv_bfloat16 g_B2rkv[(size_t)N1_*K3];  // 18.9 MB
__device__ __align__(256) __nv_bfloat16 g_B2o[(size_t)N2_*K3];    //  6.3 MB
__device__ __align__(256) float g_rkv[(size_t)M_*N1_];            // 100.7 MB
__device__ __align__(256) float g_r[(size_t)M_*HID_];             //  33.5 MB
__device__ __align__(256) float g_kv[(size_t)M_*HID_];            //  33.5 MB
__device__ __align__(256) float g_uloc[(size_t)M_*HID_];          //  33.5 MB
__device__ __align__(256) float g_T[(size_t)B_*64*HID_];          //   0.5 MB
__device__ __align__(256) float g_carry[(size_t)B_*64*HID_];      //   0.5 MB
__device__ float g_gfac;   // exp(a)
__device__ float g_apos;   // a = mean(exp(time_decay)) = -avg_decay

// ---------------------------------------------------------------------------
// helpers
// ---------------------------------------------------------------------------
__device__ __forceinline__ uint32_t smem_u32(const void* p) {
    uint32_t a;
    asm("{ .reg .u64 t; cvta.to.shared.u64 t, %1; cvt.u32.u64 %0, t; }" : "=r"(a) : "l"(p));
    return a;
}
__device__ __forceinline__ void cp16(uint32_t dst, const void* src) {
    asm volatile("cp.async.cg.shared.global [%0], [%1], 16;" :: "r"(dst), "l"(src));
}
__device__ __forceinline__ void ldm_x4(uint32_t* r, uint32_t addr) {
    asm volatile("ldmatrix.sync.aligned.m8n8.x4.shared.b16 {%0,%1,%2,%3}, [%4];"
                 : "=r"(r[0]), "=r"(r[1]), "=r"(r[2]), "=r"(r[3]) : "r"(addr));
}
__device__ __forceinline__ void mma16816(float* c, const uint32_t* a, const uint32_t* b) {
    asm volatile(
        "mma.sync.aligned.m16n8k16.row.col.f32.bf16.bf16.f32 "
        "{%0,%1,%2,%3}, {%4,%5,%6,%7}, {%8,%9}, {%0,%1,%2,%3};"
        : "+f"(c[0]), "+f"(c[1]), "+f"(c[2]), "+f"(c[3])
        : "r"(a[0]), "r"(a[1]), "r"(a[2]), "r"(a[3]), "r"(b[0]), "r"(b[1]));
}

// ---------------------------------------------------------------------------
// bf16 HMMA GEMM: C[M,N] = A[M,K3] * B[N,K3]^T, fp32 out.
// CTA tile 128(M)x256(N), BK=64, 3-stage cp.async ring, one sync per K-tile.
// 8 warps, 64x64 per warp (4 m-frags x 8 n-frags of m16n8k16).
// smem rows padded to 72 elems (144B stride: conflict-free ldmatrix/cp.async).
// ---------------------------------------------------------------------------
#define BK 64
#define NKT (K3/BK)            // 48
#define NSTG 3
#define LDS_ (BK + 8)          // 72
#define BM_T 128
#define BN_T 256
#define A_E (BM_T*LDS_)        // 9216 elems
#define B_E (BN_T*LDS_)        // 18432 elems
#define STG_B ((A_E+B_E)*2)    // 55296 B per stage
#define SMEM_DYN (NSTG*STG_B)  // 165888 B

__global__ void __launch_bounds__(256, 1)
gemm_hmma(const __nv_bfloat16* __restrict__ A,
          const __nv_bfloat16* __restrict__ Bm,
          float* __restrict__ C, int N) {
    extern __shared__ __nv_bfloat16 smem[];
    const uint32_t sb = smem_u32(smem);

    const int tid = threadIdx.x;
    const int wid = tid >> 5, lane = tid & 31;
    const int bm = blockIdx.y * BM_T;
    const int bn = blockIdx.x * BN_T;
    const int wm = (wid & 1) * 64;
    const int wn = (wid >> 1) * 64;

    float acc[4][8][4];
    #pragma unroll
    for (int i = 0; i < 4; i++)
        #pragma unroll
        for (int j = 0; j < 8; j++)
            #pragma unroll
            for (int q = 0; q < 4; q++) acc[i][j][q] = 0.f;

    // ldmatrix lane addressing (element offsets within tile)
    const int a_r = lane & 15, a_k = (lane >> 4) << 3;
    const int b_r = (lane & 7) + ((lane >> 4) << 3), b_k = ((lane >> 3) & 1) << 3;

    auto load_tile = [&](int kt, int st) {
        const size_t k0 = (size_t)kt * BK;
        uint32_t da = sb + (uint32_t)st * STG_B;
        uint32_t db = da + A_E * 2;
        #pragma unroll
        for (int j = 0; j < 4; j++) {          // A: 1024 chunks
            int c = tid + j * 256;
            int r = c >> 3, k = (c & 7) * 8;
            cp16(da + (uint32_t)(r * LDS_ + k) * 2,
                 A + (size_t)(bm + r) * K3 + k0 + k);
        }
        #pragma unroll
        for (int j = 0; j < 8; j++) {          // B: 2048 chunks
            int c = tid + j * 256;
            int r = c >> 3, k = (c & 7) * 8;
            cp16(db + (uint32_t)(r * LDS_ + k) * 2,
                 Bm + (size_t)(bn + r) * K3 + k0 + k);
        }
        asm volatile("cp.async.commit_group;" ::: "memory");
    };

    load_tile(0, 0);
    load_tile(1, 1);

    for (int kt = 0; kt < NKT; kt++) {
        const int st = kt % NSTG;
        if (kt < NKT - 1) asm volatile("cp.async.wait_group 1;" ::: "memory");
        else              asm volatile("cp.async.wait_group 0;" ::: "memory");
        __syncthreads();

        const int nt = kt + NSTG - 1;
        if (nt < NKT) load_tile(nt, nt % NSTG);

        const uint32_t da = sb + (uint32_t)st * STG_B;
        const uint32_t db = da + A_E * 2;

        #pragma unroll
        for (int ks = 0; ks < BK / 16; ks++) {
            uint32_t af[4][4];
            #pragma unroll
            for (int mi = 0; mi < 4; mi++) {
                int row = wm + mi * 16 + a_r;
                ldm_x4(af[mi], da + (uint32_t)(row * LDS_ + ks * 16 + a_k) * 2);
            }
            uint32_t bf[8][2];
            #pragma unroll
            for (int p = 0; p < 4; p++) {
                uint32_t r[4];
                int row = wn + p * 16 + b_r;
                ldm_x4(r, db + (uint32_t)(row * LDS_ + ks * 16 + b_k) * 2);
                bf[p * 2 + 0][0] = r[0]; bf[p * 2 + 0][1] = r[1];
                bf[p * 2 + 1][0] = r[2]; bf[p * 2 + 1][1] = r[3];
            }
            #pragma unroll
            for (int mi = 0; mi < 4; mi++)
                #pragma unroll
                for (int nj = 0; nj < 8; nj++)
                    mma16816(acc[mi][nj], af[mi], bf[nj]);
        }
    }

    // epilogue
    const int er = lane >> 2, ec = (lane & 3) * 2;
    #pragma unroll
    for (int mi = 0; mi < 4; mi++) {
        #pragma unroll
        for (int nj = 0; nj < 8; nj++) {
            size_t row0 = (size_t)(bm + wm + mi * 16 + er);
            size_t col  = (size_t)(bn + wn + nj * 8 + ec);
            float2 v0 = make_float2(acc[mi][nj][0], acc[mi][nj][1]);
            float2 v1 = make_float2(acc[mi][nj][2], acc[mi][nj][3]);
            *(float2*)(C + row0 * N + col)       = v0;
            *(float2*)(C + (row0 + 8) * N + col) = v1;
        }
    }
}

// ---------------------------------------------------------------------------
// bf16 split helper
// ---------------------------------------------------------------------------
__device__ __forceinline__ void split2(float x, __nv_bfloat16& h, __nv_bfloat16& l) {
    h = __float2bfloat16(x);
    l = __float2bfloat16(x - __bfloat162float(h));
}

// 1) token mix + split -> g_A2 = [ah | al | ah]
__global__ void mix_split_kernel(const float* __restrict__ hsrc,
                                 const float* __restrict__ tm) {
    int i4 = blockIdx.x * blockDim.x + threadIdx.x;
    if (i4 >= M_ * HID_ / 4) return;
    int e = i4 * 4;
    int col = e & (HID_ - 1);
    int row = e >> 10;
    int s = row & (S_ - 1);
    float4 hv = *(const float4*)(hsrc + e);
    float4 tv = *(const float4*)(tm + col);
    float4 pv = make_float4(0.f, 0.f, 0.f, 0.f);
    if (s) pv = *(const float4*)(hsrc + e - HID_);
    float m[4] = { hv.x * tv.x + pv.x * (1.f - tv.x),
                   hv.y * tv.y + pv.y * (1.f - tv.y),
                   hv.z * tv.z + pv.z * (1.f - tv.z),
                   hv.w * tv.w + pv.w * (1.f - tv.w) };
    __nv_bfloat16 h[4], l[4];
    #pragma unroll
    for (int i = 0; i < 4; i++) split2(m[i], h[i], l[i]);
    __nv_bfloat16* base = g_A2 + (size_t)row * K3 + col;
    *(uint64_t*)(base)        = *(uint64_t*)h;
    *(uint64_t*)(base + 1024) = *(uint64_t*)l;
    *(uint64_t*)(base + 2048) = *(uint64_t*)h;
}

// weight split -> out = [bh | bh | bl]
__global__ void wsplit_kernel(const float* __restrict__ W,
                              __nv_bfloat16* __restrict__ out, int rows) {
    int i4 = blockIdx.x * blockDim.x + threadIdx.x;
    if (i4 >= rows * (HID_ / 4)) return;
    int e = i4 * 4;
    int col = e & (HID_ - 1);
    int row = e >> 10;
    float4 w = *(const float4*)(W + e);
    float m[4] = { w.x, w.y, w.z, w.w };
    __nv_bfloat16 h[4], l[4];
    #pragma unroll
    for (int i = 0; i < 4; i++) split2(m[i], h[i], l[i]);
    __nv_bfloat16* base = out + (size_t)row * K3 + col;
    *(uint64_t*)(base)        = *(uint64_t*)h;
    *(uint64_t*)(base + 1024) = *(uint64_t*)h;
    *(uint64_t*)(base + 2048) = *(uint64_t*)l;
}

// 4) scalar decay factor: a = mean(exp(td)), g = exp(a)
__global__ void prep_kernel(const float* __restrict__ td) {
    __shared__ float red[256];
    float s = 0.f;
    for (int i = threadIdx.x; i < H_ * D_; i += 256) s += expf(td[i]);
    red[threadIdx.x] = s;
    __syncthreads();
    for (int w = 128; w > 0; w >>= 1) {
        if (threadIdx.x < w) red[threadIdx.x] += red[threadIdx.x + w];
        __syncthreads();
    }
    if (threadIdx.x == 0) {
        float a = red[0] / (float)(H_ * D_);
        g_apos = a;
        g_gfac = expf(a);
    }
}

// 5a) FUSED: sigmoid + RoPE + kv=k*v + local suffix scan over 64-chunks
__global__ void scanA_kernel(const float* __restrict__ cosb,
                             const float* __restrict__ sinb) {
    int gid = blockIdx.x * blockDim.x + threadIdx.x;   // B_*64*HID_ = 131072
    int ch = gid & (HID_ - 1);
    int c  = (gid >> 10) & 63;
    int b  = gid >> 16;
    int d  = ch & 63;
    int pd = ch ^ 32;
    float sign = (d < 32) ? -1.f : 1.f;
    float g = g_gfac;

    float u = 0.f;
    #pragma unroll 2
    for (int p = 63; p >= 0; p--) {
        int s = c * 64 + p;
        size_t row = (size_t)b * S_ + s;
        const float* base = g_rkv + row * N1_;

        float rv  = base[ch];
        float rpv = base[pd];
        float kvv = base[1024 + ch];
        float kpv = base[1024 + pd];
        float vv  = base[2048 + ch];

        float cc = cosb[s * 64 + d];
        float sn = sinb[s * 64 + d];

        float rs  = 1.f / (1.f + __expf(-rv));
        float rps = 1.f / (1.f + __expf(-rpv));
        float rr  = rs * cc + sign * rps * sn;
        float kk  = kvv * cc + sign * kpv * sn;
        float kvp = kk * vv;

        size_t idx = row * HID_ + ch;
        g_r[idx]  = rr;
        g_kv[idx] = kvp;
        u = fmaf(g, u, kvp);
        g_uloc[idx] = u;
    }
    g_T[gid] = u;
}

// 5b) chunk-carry suffix combine (per channel)
__global__ void scanB_kernel() {
    int t = blockIdx.x * blockDim.x + threadIdx.x;     // B_*HID_ = 2048
    if (t >= B_ * HID_) return;
    int ch = t & (HID_ - 1);
    int b  = t >> 10;
    float gL = expf(g_apos * 64.f);
    float usuf = 0.f;
    for (int c = 63; c >= 0; c--) {
        int i = (b * 64 + c) * HID_ + ch;
        g_carry[i] = usuf;
        usuf = fmaf(gL, usuf, g_T[i]);
    }
}

// 5c) finalize: U = uloc + g^(64-p)*carry, den closed-form, gate, split -> g_A2
__global__ void scanC_kernel(const float* __restrict__ tf) {
    int idx = blockIdx.x * blockDim.x + threadIdx.x;   // M_*HID_
    if (idx >= M_ * HID_) return;
    int ch = idx & (HID_ - 1);
    int s  = (idx >> 10) & (S_ - 1);
    int b  = idx >> 22;
    int p  = s & 63;
    int c  = s >> 6;
    float a = g_apos;
    float carry = g_carry[(b * 64 + c) * HID_ + ch];
    float U = g_uloc[idx] + expf(a * (float)(64 - p)) * carry;
    float den = expm1f(a * (float)(S_ - s)) / expm1f(a);
    float wkv = U / (den + 1e-8f);
    float att = g_r[idx] * (tf[ch] * g_kv[idx] + wkv);
    __nv_bfloat16 h, l;
    split2(att, h, l);
    int row = idx >> 10;
    __nv_bfloat16* base = g_A2 + (size_t)row * K3 + ch;
    base[0]    = h;
    base[1024] = l;
    base[2048] = h;
}

// ---------------------------------------------------------------------------
// launch
// ---------------------------------------------------------------------------
extern "C" void kernel_launch(void* const* d_in, const int* in_sizes, int n_in,
                              void* d_out, int out_size) {
    const float* hidden = (const float*)d_in[0];
    const float* cosb   = (const float*)d_in[1];
    const float* sinb   = (const float*)d_in[2];
    const float* W_rkv  = (const float*)d_in[3];
    const float* W_o    = (const float*)d_in[4];
    const float* tdec   = (const float*)d_in[5];
    const float* tfirst = (const float*)d_in[6];
    const float* tmix   = (const float*)d_in[7];
    float* out = (float*)d_out;

    __nv_bfloat16 *A2, *B2rkv, *B2o;
    float *rkv;
    cudaGetSymbolAddress((void**)&A2,    g_A2);
    cudaGetSymbolAddress((void**)&B2rkv, g_B2rkv);
    cudaGetSymbolAddress((void**)&B2o,   g_B2o);
    cudaGetSymbolAddress((void**)&rkv,   g_rkv);

    cudaFuncSetAttribute(gemm_hmma,
                         cudaFuncAttributeMaxDynamicSharedMemorySize, SMEM_DYN);

    // scalar decay factor (independent)
    prep_kernel<<<1, 256>>>(tdec);

    // token mix + split
    mix_split_kernel<<<(M_ * HID_ / 4 + 255) / 256, 256>>>(hidden, tmix);

    // weight splits
    wsplit_kernel<<<(N1_ * HID_ / 4 + 255) / 256, 256>>>(W_rkv, B2rkv, N1_);
    wsplit_kernel<<<(N2_ * HID_ / 4 + 255) / 256, 256>>>(W_o,   B2o,   N2_);

    // GEMM1: rkv = mixed @ W_rkv^T  (HMMA, split-bf16)
    gemm_hmma<<<dim3(N1_ / BN_T, M_ / BM_T), 256, SMEM_DYN>>>(A2, B2rkv, rkv, N1_);

    // fused rope/sigmoid/kv + local scan
    scanA_kernel<<<(B_ * 64 * HID_) / 256, 256>>>(cosb, sinb);
    scanB_kernel<<<(B_ * HID_ + 255) / 256, 256>>>();
    scanC_kernel<<<(M_ * HID_ + 255) / 256, 256>>>(tfirst);

    // GEMM2: out = att @ W_o^T  (HMMA, split-bf16)
    gemm_hmma<<<dim3(N2_ / BN_T, M_ / BM_T), 256, SMEM_DYN>>>(A2, B2o, out, N2_);
}

// round 11
// speedup vs baseline: 1.0897x; 1.0897x over previous
#include <cuda_runtime.h>
#include <cuda_bf16.h>
#include <stdint.h>
#include <math.h>

// Problem constants
#define B_   2
#define S_   4096
#define HID_ 1024
#define H_   16
#define D_   64
#define M_   (B_*S_)        // 8192
#define N1_  (3*H_*D_)      // 3072
#define N2_  HID_           // 1024
#define K3   3072           // split-K': [ah|al|ah] x [bh|bh|bl]

// ---------------------------------------------------------------------------
// Scratch (no cudaMalloc allowed)
// ---------------------------------------------------------------------------
__device__ __align__(256) __nv_bfloat16 g_A2[(size_t)M_*K3];      // 50.3 MB
__device__ __align__(256) __nv_bfloat16 g_B2rkv[(size_t)N1_*K3];  // 18.9 MB
__device__ __align__(256) __nv_bfloat16 g_B2o[(size_t)N2_*K3];    //  6.3 MB
__device__ __align__(256) float g_rkv[(size_t)M_*N1_];            // 100.7 MB
__device__ __align__(256) float g_r[(size_t)M_*HID_];             //  33.5 MB
__device__ __align__(256) float g_kv[(size_t)M_*HID_];            //  33.5 MB
__device__ __align__(256) float g_uloc[(size_t)M_*HID_];          //  33.5 MB
__device__ __align__(256) float g_T[(size_t)B_*64*HID_];          //   0.5 MB
__device__ __align__(256) float g_carry[(size_t)B_*64*HID_];      //   0.5 MB
__device__ float g_gfac;   // exp(a)
__device__ float g_apos;   // a = mean(exp(time_decay)) = -avg_decay

// ---------------------------------------------------------------------------
// helpers
// ---------------------------------------------------------------------------
__device__ __forceinline__ uint32_t smem_u32(const void* p) {
    uint32_t a;
    asm("{ .reg .u64 t; cvta.to.shared.u64 t, %1; cvt.u32.u64 %0, t; }" : "=r"(a) : "l"(p));
    return a;
}
__device__ __forceinline__ void cp16(uint32_t dst, const void* src) {
    asm volatile("cp.async.cg.shared.global [%0], [%1], 16;" :: "r"(dst), "l"(src));
}
__device__ __forceinline__ void ldm_x4(uint32_t* r, uint32_t addr) {
    asm volatile("ldmatrix.sync.aligned.m8n8.x4.shared.b16 {%0,%1,%2,%3}, [%4];"
                 : "=r"(r[0]), "=r"(r[1]), "=r"(r[2]), "=r"(r[3]) : "r"(addr));
}
__device__ __forceinline__ void mma16816(float* c, const uint32_t* a, const uint32_t* b) {
    asm volatile(
        "mma.sync.aligned.m16n8k16.row.col.f32.bf16.bf16.f32 "
        "{%0,%1,%2,%3}, {%4,%5,%6,%7}, {%8,%9}, {%0,%1,%2,%3};"
        : "+f"(c[0]), "+f"(c[1]), "+f"(c[2]), "+f"(c[3])
        : "r"(a[0]), "r"(a[1]), "r"(a[2]), "r"(a[3]), "r"(b[0]), "r"(b[1]));
}

// ---------------------------------------------------------------------------
// bf16 HMMA GEMM: C[M,N] = A[M,K3] * B[N,K3]^T, fp32 out.
// CTA tile 128x128, BK=64, 3-stage cp.async ring, ONE sync per K-tile.
// 4 warps (128 threads), 64x64 per warp (4 m-frags x 8 n-frags m16n8k16).
// -> mma:ldsm = 4.0 per k-step AND 2 CTAs/SM (regs ~190*128=24.3K/CTA,
//    smem 110.6KB/CTA; both fit x2).
// smem rows padded to 72 elems (144B stride: conflict-free ldmatrix/cp.async).
// ---------------------------------------------------------------------------
#define BK 64
#define NKT (K3/BK)            // 48
#define NSTG 3
#define LDS_ (BK + 8)          // 72
#define BM_T 128
#define BN_T 128
#define A_E (BM_T*LDS_)        // 9216 elems
#define B_E (BN_T*LDS_)        // 9216 elems
#define STG_B ((A_E+B_E)*2)    // 36864 B per stage
#define SMEM_DYN (NSTG*STG_B)  // 110592 B

__global__ void __launch_bounds__(128, 2)
gemm_hmma(const __nv_bfloat16* __restrict__ A,
          const __nv_bfloat16* __restrict__ Bm,
          float* __restrict__ C, int N) {
    extern __shared__ __nv_bfloat16 smem[];
    const uint32_t sb = smem_u32(smem);

    const int tid = threadIdx.x;
    const int wid = tid >> 5, lane = tid & 31;
    const int bm = blockIdx.y * BM_T;
    const int bn = blockIdx.x * BN_T;
    const int wm = (wid & 1) * 64;
    const int wn = (wid >> 1) * 64;

    float acc[4][8][4];
    #pragma unroll
    for (int i = 0; i < 4; i++)
        #pragma unroll
        for (int j = 0; j < 8; j++)
            #pragma unroll
            for (int q = 0; q < 4; q++) acc[i][j][q] = 0.f;

    // ldmatrix lane addressing (element offsets within tile)
    const int a_r = lane & 15, a_k = (lane >> 4) << 3;
    const int b_r = (lane & 7) + ((lane >> 4) << 3), b_k = ((lane >> 3) & 1) << 3;

    auto load_tile = [&](int kt, int st) {
        const size_t k0 = (size_t)kt * BK;
        uint32_t da = sb + (uint32_t)st * STG_B;
        uint32_t db = da + A_E * 2;
        #pragma unroll
        for (int j = 0; j < 8; j++) {          // A: 1024 chunks / 128 thr
            int c = tid + j * 128;
            int r = c >> 3, k = (c & 7) * 8;
            cp16(da + (uint32_t)(r * LDS_ + k) * 2,
                 A + (size_t)(bm + r) * K3 + k0 + k);
        }
        #pragma unroll
        for (int j = 0; j < 8; j++) {          // B: 1024 chunks / 128 thr
            int c = tid + j * 128;
            int r = c >> 3, k = (c & 7) * 8;
            cp16(db + (uint32_t)(r * LDS_ + k) * 2,
                 Bm + (size_t)(bn + r) * K3 + k0 + k);
        }
        asm volatile("cp.async.commit_group;" ::: "memory");
    };

    load_tile(0, 0);
    load_tile(1, 1);

    for (int kt = 0; kt < NKT; kt++) {
        const int st = kt % NSTG;
        if (kt < NKT - 1) asm volatile("cp.async.wait_group 1;" ::: "memory");
        else              asm volatile("cp.async.wait_group 0;" ::: "memory");
        __syncthreads();

        const int nt = kt + NSTG - 1;
        if (nt < NKT) load_tile(nt, nt % NSTG);

        const uint32_t da = sb + (uint32_t)st * STG_B;
        const uint32_t db = da + A_E * 2;

        #pragma unroll
        for (int ks = 0; ks < BK / 16; ks++) {
            uint32_t af[4][4];
            #pragma unroll
            for (int mi = 0; mi < 4; mi++) {
                int row = wm + mi * 16 + a_r;
                ldm_x4(af[mi], da + (uint32_t)(row * LDS_ + ks * 16 + a_k) * 2);
            }
            uint32_t bf[8][2];
            #pragma unroll
            for (int p = 0; p < 4; p++) {
                uint32_t r[4];
                int row = wn + p * 16 + b_r;
                ldm_x4(r, db + (uint32_t)(row * LDS_ + ks * 16 + b_k) * 2);
                bf[p * 2 + 0][0] = r[0]; bf[p * 2 + 0][1] = r[1];
                bf[p * 2 + 1][0] = r[2]; bf[p * 2 + 1][1] = r[3];
            }
            #pragma unroll
            for (int mi = 0; mi < 4; mi++)
                #pragma unroll
                for (int nj = 0; nj < 8; nj++)
                    mma16816(acc[mi][nj], af[mi], bf[nj]);
        }
    }

    // epilogue
    const int er = lane >> 2, ec = (lane & 3) * 2;
    #pragma unroll
    for (int mi = 0; mi < 4; mi++) {
        #pragma unroll
        for (int nj = 0; nj < 8; nj++) {
            size_t row0 = (size_t)(bm + wm + mi * 16 + er);
            size_t col  = (size_t)(bn + wn + nj * 8 + ec);
            float2 v0 = make_float2(acc[mi][nj][0], acc[mi][nj][1]);
            float2 v1 = make_float2(acc[mi][nj][2], acc[mi][nj][3]);
            *(float2*)(C + row0 * N + col)       = v0;
            *(float2*)(C + (row0 + 8) * N + col) = v1;
        }
    }
}

// ---------------------------------------------------------------------------
// bf16 split helper
// ---------------------------------------------------------------------------
__device__ __forceinline__ void split2(float x, __nv_bfloat16& h, __nv_bfloat16& l) {
    h = __float2bfloat16(x);
    l = __float2bfloat16(x - __bfloat162float(h));
}

// 1) token mix + split -> g_A2 = [ah | al | ah]
__global__ void mix_split_kernel(const float* __restrict__ hsrc,
                                 const float* __restrict__ tm) {
    int i4 = blockIdx.x * blockDim.x + threadIdx.x;
    if (i4 >= M_ * HID_ / 4) return;
    int e = i4 * 4;
    int col = e & (HID_ - 1);
    int row = e >> 10;
    int s = row & (S_ - 1);
    float4 hv = *(const float4*)(hsrc + e);
    float4 tv = *(const float4*)(tm + col);
    float4 pv = make_float4(0.f, 0.f, 0.f, 0.f);
    if (s) pv = *(const float4*)(hsrc + e - HID_);
    float m[4] = { hv.x * tv.x + pv.x * (1.f - tv.x),
                   hv.y * tv.y + pv.y * (1.f - tv.y),
                   hv.z * tv.z + pv.z * (1.f - tv.z),
                   hv.w * tv.w + pv.w * (1.f - tv.w) };
    __nv_bfloat16 h[4], l[4];
    #pragma unroll
    for (int i = 0; i < 4; i++) split2(m[i], h[i], l[i]);
    __nv_bfloat16* base = g_A2 + (size_t)row * K3 + col;
    *(uint64_t*)(base)        = *(uint64_t*)h;
    *(uint64_t*)(base + 1024) = *(uint64_t*)l;
    *(uint64_t*)(base + 2048) = *(uint64_t*)h;
}

// weight split -> out = [bh | bh | bl]
__global__ void wsplit_kernel(const float* __restrict__ W,
                              __nv_bfloat16* __restrict__ out, int rows) {
    int i4 = blockIdx.x * blockDim.x + threadIdx.x;
    if (i4 >= rows * (HID_ / 4)) return;
    int e = i4 * 4;
    int col = e & (HID_ - 1);
    int row = e >> 10;
    float4 w = *(const float4*)(W + e);
    float m[4] = { w.x, w.y, w.z, w.w };
    __nv_bfloat16 h[4], l[4];
    #pragma unroll
    for (int i = 0; i < 4; i++) split2(m[i], h[i], l[i]);
    __nv_bfloat16* base = out + (size_t)row * K3 + col;
    *(uint64_t*)(base)        = *(uint64_t*)h;
    *(uint64_t*)(base + 1024) = *(uint64_t*)h;
    *(uint64_t*)(base + 2048) = *(uint64_t*)l;
}

// 4) scalar decay factor: a = mean(exp(td)), g = exp(a)
__global__ void prep_kernel(const float* __restrict__ td) {
    __shared__ float red[256];
    float s = 0.f;
    for (int i = threadIdx.x; i < H_ * D_; i += 256) s += expf(td[i]);
    red[threadIdx.x] = s;
    __syncthreads();
    for (int w = 128; w > 0; w >>= 1) {
        if (threadIdx.x < w) red[threadIdx.x] += red[threadIdx.x + w];
        __syncthreads();
    }
    if (threadIdx.x == 0) {
        float a = red[0] / (float)(H_ * D_);
        g_apos = a;
        g_gfac = expf(a);
    }
}

// 5a) FUSED: sigmoid + RoPE + kv=k*v + local suffix scan over 64-chunks
__global__ void scanA_kernel(const float* __restrict__ cosb,
                             const float* __restrict__ sinb) {
    int gid = blockIdx.x * blockDim.x + threadIdx.x;   // B_*64*HID_ = 131072
    int ch = gid & (HID_ - 1);
    int c  = (gid >> 10) & 63;
    int b  = gid >> 16;
    int d  = ch & 63;
    int pd = ch ^ 32;
    float sign = (d < 32) ? -1.f : 1.f;
    float g = g_gfac;

    float u = 0.f;
    #pragma unroll 2
    for (int p = 63; p >= 0; p--) {
        int s = c * 64 + p;
        size_t row = (size_t)b * S_ + s;
        const float* base = g_rkv + row * N1_;

        float rv  = base[ch];
        float rpv = base[pd];
        float kvv = base[1024 + ch];
        float kpv = base[1024 + pd];
        float vv  = base[2048 + ch];

        float cc = cosb[s * 64 + d];
        float sn = sinb[s * 64 + d];

        float rs  = 1.f / (1.f + __expf(-rv));
        float rps = 1.f / (1.f + __expf(-rpv));
        float rr  = rs * cc + sign * rps * sn;
        float kk  = kvv * cc + sign * kpv * sn;
        float kvp = kk * vv;

        size_t idx = row * HID_ + ch;
        g_r[idx]  = rr;
        g_kv[idx] = kvp;
        u = fmaf(g, u, kvp);
        g_uloc[idx] = u;
    }
    g_T[gid] = u;
}

// 5b) chunk-carry suffix combine (per channel)
__global__ void scanB_kernel() {
    int t = blockIdx.x * blockDim.x + threadIdx.x;     // B_*HID_ = 2048
    if (t >= B_ * HID_) return;
    int ch = t & (HID_ - 1);
    int b  = t >> 10;
    float gL = expf(g_apos * 64.f);
    float usuf = 0.f;
    for (int c = 63; c >= 0; c--) {
        int i = (b * 64 + c) * HID_ + ch;
        g_carry[i] = usuf;
        usuf = fmaf(gL, usuf, g_T[i]);
    }
}

// 5c) finalize: U = uloc + g^(64-p)*carry, den closed-form, gate, split -> g_A2
__global__ void scanC_kernel(const float* __restrict__ tf) {
    int idx = blockIdx.x * blockDim.x + threadIdx.x;   // M_*HID_
    if (idx >= M_ * HID_) return;
    int ch = idx & (HID_ - 1);
    int s  = (idx >> 10) & (S_ - 1);
    int b  = idx >> 22;
    int p  = s & 63;
    int c  = s >> 6;
    float a = g_apos;
    float carry = g_carry[(b * 64 + c) * HID_ + ch];
    float U = g_uloc[idx] + expf(a * (float)(64 - p)) * carry;
    float den = expm1f(a * (float)(S_ - s)) / expm1f(a);
    float wkv = U / (den + 1e-8f);
    float att = g_r[idx] * (tf[ch] * g_kv[idx] + wkv);
    __nv_bfloat16 h, l;
    split2(att, h, l);
    int row = idx >> 10;
    __nv_bfloat16* base = g_A2 + (size_t)row * K3 + ch;
    base[0]    = h;
    base[1024] = l;
    base[2048] = h;
}

// ---------------------------------------------------------------------------
// launch
// ---------------------------------------------------------------------------
extern "C" void kernel_launch(void* const* d_in, const int* in_sizes, int n_in,
                              void* d_out, int out_size) {
    const float* hidden = (const float*)d_in[0];
    const float* cosb   = (const float*)d_in[1];
    const float* sinb   = (const float*)d_in[2];
    const float* W_rkv  = (const float*)d_in[3];
    const float* W_o    = (const float*)d_in[4];
    const float* tdec   = (const float*)d_in[5];
    const float* tfirst = (const float*)d_in[6];
    const float* tmix   = (const float*)d_in[7];
    float* out = (float*)d_out;

    __nv_bfloat16 *A2, *B2rkv, *B2o;
    float *rkv;
    cudaGetSymbolAddress((void**)&A2,    g_A2);
    cudaGetSymbolAddress((void**)&B2rkv, g_B2rkv);
    cudaGetSymbolAddress((void**)&B2o,   g_B2o);
    cudaGetSymbolAddress((void**)&rkv,   g_rkv);

    cudaFuncSetAttribute(gemm_hmma,
                         cudaFuncAttributeMaxDynamicSharedMemorySize, SMEM_DYN);

    // (1) scalar decay factor
    prep_kernel<<<1, 256>>>(tdec);
    // (2) token mix + split
    mix_split_kernel<<<(M_ * HID_ / 4 + 255) / 256, 256>>>(hidden, tmix);
    // (3) W_rkv split
    wsplit_kernel<<<(N1_ * HID_ / 4 + 255) / 256, 256>>>(W_rkv, B2rkv, N1_);
    // (4) GEMM1: rkv = mixed @ W_rkv^T
    gemm_hmma<<<dim3(N1_ / BN_T, M_ / BM_T), 128, SMEM_DYN>>>(A2, B2rkv, rkv, N1_);
    // (5) W_o split (independent of GEMM1 result)
    wsplit_kernel<<<(N2_ * HID_ / 4 + 255) / 256, 256>>>(W_o, B2o, N2_);
    // (6) fused rope/sigmoid/kv + local scan
    scanA_kernel<<<(B_ * 64 * HID_) / 256, 256>>>(cosb, sinb);
    // (7) chunk-carry combine
    scanB_kernel<<<(B_ * HID_ + 255) / 256, 256>>>();
    // (8) finalize + gate + split
    scanC_kernel<<<(M_ * HID_ + 255) / 256, 256>>>(tfirst);
    // (9) GEMM2: out = att @ W_o^T
    gemm_hmma<<<dim3(N2_ / BN_T, M_ / BM_T), 128, SMEM_DYN>>>(A2, B2o, out, N2_);
}

// round 12
// speedup vs baseline: 1.4834x; 1.3612x over previous
#include <cuda_runtime.h>
#include <cuda_fp16.h>
#include <stdint.h>
#include <math.h>

// Problem constants
#define B_   2
#define S_   4096
#define HID_ 1024
#define H_   16
#define D_   64
#define M_   (B_*S_)        // 8192
#define N1_  (3*H_*D_)      // 3072
#define N2_  HID_           // 1024
#define KSP  2048           // fp16 2-term split-K': [ah|al] x [bh|bh]

// ---------------------------------------------------------------------------
// Scratch (no cudaMalloc allowed)
// ---------------------------------------------------------------------------
__device__ __align__(256) __half g_A2[(size_t)M_*KSP];        // 33.5 MB
__device__ __align__(256) __half g_B2rkv[(size_t)N1_*KSP];    // 12.6 MB
__device__ __align__(256) __half g_B2o[(size_t)N2_*KSP];      //  4.2 MB
__device__ __align__(256) float g_rkv[(size_t)M_*N1_];        // 100.7 MB
__device__ __align__(256) float g_r[(size_t)M_*HID_];         //  33.5 MB
__device__ __align__(256) float g_kv[(size_t)M_*HID_];        //  33.5 MB
__device__ __align__(256) float g_uloc[(size_t)M_*HID_];      //  33.5 MB
__device__ __align__(256) float g_T[(size_t)B_*64*HID_];      //   0.5 MB
__device__ __align__(256) float g_carry[(size_t)B_*64*HID_];  //   0.5 MB
__device__ float g_gfac;   // exp(a)
__device__ float g_apos;   // a = mean(exp(time_decay)) = -avg_decay

// ---------------------------------------------------------------------------
// helpers
// ---------------------------------------------------------------------------
__device__ __forceinline__ uint32_t smem_u32(const void* p) {
    uint32_t a;
    asm("{ .reg .u64 t; cvta.to.shared.u64 t, %1; cvt.u32.u64 %0, t; }" : "=r"(a) : "l"(p));
    return a;
}
__device__ __forceinline__ void cp16(uint32_t dst, const void* src) {
    asm volatile("cp.async.cg.shared.global [%0], [%1], 16;" :: "r"(dst), "l"(src));
}
__device__ __forceinline__ void ldm_x4(uint32_t* r, uint32_t addr) {
    asm volatile("ldmatrix.sync.aligned.m8n8.x4.shared.b16 {%0,%1,%2,%3}, [%4];"
                 : "=r"(r[0]), "=r"(r[1]), "=r"(r[2]), "=r"(r[3]) : "r"(addr));
}
__device__ __forceinline__ void mma16816(float* c, const uint32_t* a, const uint32_t* b) {
    asm volatile(
        "mma.sync.aligned.m16n8k16.row.col.f32.f16.f16.f32 "
        "{%0,%1,%2,%3}, {%4,%5,%6,%7}, {%8,%9}, {%0,%1,%2,%3};"
        : "+f"(c[0]), "+f"(c[1]), "+f"(c[2]), "+f"(c[3])
        : "r"(a[0]), "r"(a[1]), "r"(a[2]), "r"(a[3]), "r"(b[0]), "r"(b[1]));
}

// ---------------------------------------------------------------------------
// fp16 HMMA GEMM: C[M,N] = A[M,KSP] * B[N,KSP]^T, fp32 out.
// CTA tile 128x128, BK=64, 3-stage cp.async ring, ONE sync per K-tile.
// 4 warps (128 threads), 64x64 per warp (4 m-frags x 8 n-frags m16n8k16).
// 2 CTAs/SM (regs ~226*128=29K/CTA, smem 110.6KB/CTA).
// ---------------------------------------------------------------------------
#define BK 64
#define NKT (KSP/BK)           // 32
#define NSTG 3
#define LDS_ (BK + 8)          // 72
#define BM_T 128
#define BN_T 128
#define A_E (BM_T*LDS_)        // 9216 elems
#define B_E (BN_T*LDS_)        // 9216 elems
#define STG_B ((A_E+B_E)*2)    // 36864 B per stage
#define SMEM_DYN (NSTG*STG_B)  // 110592 B

__global__ void __launch_bounds__(128, 2)
gemm_hmma(const __half* __restrict__ A,
          const __half* __restrict__ Bm,
          float* __restrict__ C, int N) {
    extern __shared__ __half smem[];
    const uint32_t sb = smem_u32(smem);

    const int tid = threadIdx.x;
    const int wid = tid >> 5, lane = tid & 31;
    const int bm = blockIdx.y * BM_T;
    const int bn = blockIdx.x * BN_T;
    const int wm = (wid & 1) * 64;
    const int wn = (wid >> 1) * 64;

    float acc[4][8][4];
    #pragma unroll
    for (int i = 0; i < 4; i++)
        #pragma unroll
        for (int j = 0; j < 8; j++)
            #pragma unroll
            for (int q = 0; q < 4; q++) acc[i][j][q] = 0.f;

    const int a_r = lane & 15, a_k = (lane >> 4) << 3;
    const int b_r = (lane & 7) + ((lane >> 4) << 3), b_k = ((lane >> 3) & 1) << 3;

    auto load_tile = [&](int kt, int st) {
        const size_t k0 = (size_t)kt * BK;
        uint32_t da = sb + (uint32_t)st * STG_B;
        uint32_t db = da + A_E * 2;
        #pragma unroll
        for (int j = 0; j < 8; j++) {          // A: 1024 chunks / 128 thr
            int c = tid + j * 128;
            int r = c >> 3, k = (c & 7) * 8;
            cp16(da + (uint32_t)(r * LDS_ + k) * 2,
                 A + (size_t)(bm + r) * KSP + k0 + k);
        }
        #pragma unroll
        for (int j = 0; j < 8; j++) {          // B: 1024 chunks / 128 thr
            int c = tid + j * 128;
            int r = c >> 3, k = (c & 7) * 8;
            cp16(db + (uint32_t)(r * LDS_ + k) * 2,
                 Bm + (size_t)(bn + r) * KSP + k0 + k);
        }
        asm volatile("cp.async.commit_group;" ::: "memory");
    };

    load_tile(0, 0);
    load_tile(1, 1);

    for (int kt = 0; kt < NKT; kt++) {
        const int st = kt % NSTG;
        if (kt < NKT - 1) asm volatile("cp.async.wait_group 1;" ::: "memory");
        else              asm volatile("cp.async.wait_group 0;" ::: "memory");
        __syncthreads();

        const int nt = kt + NSTG - 1;
        if (nt < NKT) load_tile(nt, nt % NSTG);

        const uint32_t da = sb + (uint32_t)st * STG_B;
        const uint32_t db = da + A_E * 2;

        #pragma unroll
        for (int ks = 0; ks < BK / 16; ks++) {
            uint32_t af[4][4];
            #pragma unroll
            for (int mi = 0; mi < 4; mi++) {
                int row = wm + mi * 16 + a_r;
                ldm_x4(af[mi], da + (uint32_t)(row * LDS_ + ks * 16 + a_k) * 2);
            }
            uint32_t bf[8][2];
            #pragma unroll
            for (int p = 0; p < 4; p++) {
                uint32_t r[4];
                int row = wn + p * 16 + b_r;
                ldm_x4(r, db + (uint32_t)(row * LDS_ + ks * 16 + b_k) * 2);
                bf[p * 2 + 0][0] = r[0]; bf[p * 2 + 0][1] = r[1];
                bf[p * 2 + 1][0] = r[2]; bf[p * 2 + 1][1] = r[3];
            }
            #pragma unroll
            for (int mi = 0; mi < 4; mi++)
                #pragma unroll
                for (int nj = 0; nj < 8; nj++)
                    mma16816(acc[mi][nj], af[mi], bf[nj]);
        }
    }

    // epilogue
    const int er = lane >> 2, ec = (lane & 3) * 2;
    #pragma unroll
    for (int mi = 0; mi < 4; mi++) {
        #pragma unroll
        for (int nj = 0; nj < 8; nj++) {
            size_t row0 = (size_t)(bm + wm + mi * 16 + er);
            size_t col  = (size_t)(bn + wn + nj * 8 + ec);
            float2 v0 = make_float2(acc[mi][nj][0], acc[mi][nj][1]);
            float2 v1 = make_float2(acc[mi][nj][2], acc[mi][nj][3]);
            *(float2*)(C + row0 * N + col)       = v0;
            *(float2*)(C + (row0 + 8) * N + col) = v1;
        }
    }
}

// ---------------------------------------------------------------------------
// fp16 split helper
// ---------------------------------------------------------------------------
__device__ __forceinline__ void split2h(float x, __half& h, __half& l) {
    h = __float2half_rn(x);
    l = __float2half_rn(x - __half2float(h));
}

// 1) token mix + split -> g_A2 = [ah | al]
__global__ void mix_split_kernel(const float* __restrict__ hsrc,
                                 const float* __restrict__ tm) {
    int i4 = blockIdx.x * blockDim.x + threadIdx.x;
    if (i4 >= M_ * HID_ / 4) return;
    int e = i4 * 4;
    int col = e & (HID_ - 1);
    int row = e >> 10;
    int s = row & (S_ - 1);
    float4 hv = *(const float4*)(hsrc + e);
    float4 tv = *(const float4*)(tm + col);
    float4 pv = make_float4(0.f, 0.f, 0.f, 0.f);
    if (s) pv = *(const float4*)(hsrc + e - HID_);
    float m[4] = { hv.x * tv.x + pv.x * (1.f - tv.x),
                   hv.y * tv.y + pv.y * (1.f - tv.y),
                   hv.z * tv.z + pv.z * (1.f - tv.z),
                   hv.w * tv.w + pv.w * (1.f - tv.w) };
    __half h[4], l[4];
    #pragma unroll
    for (int i = 0; i < 4; i++) split2h(m[i], h[i], l[i]);
    __half* base = g_A2 + (size_t)row * KSP + col;
    *(uint64_t*)(base)        = *(uint64_t*)h;
    *(uint64_t*)(base + 1024) = *(uint64_t*)l;
}

// weight split -> out = [bh | bh]
__global__ void wsplit_kernel(const float* __restrict__ W,
                              __half* __restrict__ out, int rows) {
    int i4 = blockIdx.x * blockDim.x + threadIdx.x;
    if (i4 >= rows * (HID_ / 4)) return;
    int e = i4 * 4;
    int col = e & (HID_ - 1);
    int row = e >> 10;
    float4 w = *(const float4*)(W + e);
    float m[4] = { w.x, w.y, w.z, w.w };
    __half h[4];
    #pragma unroll
    for (int i = 0; i < 4; i++) h[i] = __float2half_rn(m[i]);
    __half* base = out + (size_t)row * KSP + col;
    *(uint64_t*)(base)        = *(uint64_t*)h;
    *(uint64_t*)(base + 1024) = *(uint64_t*)h;
}

// 4) scalar decay factor: a = mean(exp(td)), g = exp(a)
__global__ void prep_kernel(const float* __restrict__ td) {
    __shared__ float red[256];
    float s = 0.f;
    for (int i = threadIdx.x; i < H_ * D_; i += 256) s += expf(td[i]);
    red[threadIdx.x] = s;
    __syncthreads();
    for (int w = 128; w > 0; w >>= 1) {
        if (threadIdx.x < w) red[threadIdx.x] += red[threadIdx.x + w];
        __syncthreads();
    }
    if (threadIdx.x == 0) {
        float a = red[0] / (float)(H_ * D_);
        g_apos = a;
        g_gfac = expf(a);
    }
}

// 5a) FUSED: sigmoid + RoPE + kv=k*v + local suffix scan over 64-chunks
__global__ void scanA_kernel(const float* __restrict__ cosb,
                             const float* __restrict__ sinb) {
    int gid = blockIdx.x * blockDim.x + threadIdx.x;   // B_*64*HID_ = 131072
    int ch = gid & (HID_ - 1);
    int c  = (gid >> 10) & 63;
    int b  = gid >> 16;
    int d  = ch & 63;
    int pd = ch ^ 32;
    float sign = (d < 32) ? -1.f : 1.f;
    float g = g_gfac;

    float u = 0.f;
    #pragma unroll 2
    for (int p = 63; p >= 0; p--) {
        int s = c * 64 + p;
        size_t row = (size_t)b * S_ + s;
        const float* base = g_rkv + row * N1_;

        float rv  = base[ch];
        float rpv = base[pd];
        float kvv = base[1024 + ch];
        float kpv = base[1024 + pd];
        float vv  = base[2048 + ch];

        float cc = cosb[s * 64 + d];
        float sn = sinb[s * 64 + d];

        float rs  = 1.f / (1.f + __expf(-rv));
        float rps = 1.f / (1.f + __expf(-rpv));
        float rr  = rs * cc + sign * rps * sn;
        float kk  = kvv * cc + sign * kpv * sn;
        float kvp = kk * vv;

        size_t idx = row * HID_ + ch;
        g_r[idx]  = rr;
        g_kv[idx] = kvp;
        u = fmaf(g, u, kvp);
        g_uloc[idx] = u;
    }
    g_T[gid] = u;
}

// 5b) chunk-carry suffix combine (per channel)
__global__ void scanB_kernel() {
    int t = blockIdx.x * blockDim.x + threadIdx.x;     // B_*HID_ = 2048
    if (t >= B_ * HID_) return;
    int ch = t & (HID_ - 1);
    int b  = t >> 10;
    float gL = expf(g_apos * 64.f);
    float usuf = 0.f;
    for (int c = 63; c >= 0; c--) {
        int i = (b * 64 + c) * HID_ + ch;
        g_carry[i] = usuf;
        usuf = fmaf(gL, usuf, g_T[i]);
    }
}

// 5c) finalize: U = uloc + g^(64-p)*carry, den closed-form, gate, split -> g_A2
__global__ void scanC_kernel(const float* __restrict__ tf) {
    int idx = blockIdx.x * blockDim.x + threadIdx.x;   // M_*HID_
    if (idx >= M_ * HID_) return;
    int ch = idx & (HID_ - 1);
    int s  = (idx >> 10) & (S_ - 1);
    int b  = idx >> 22;
    int p  = s & 63;
    int c  = s >> 6;
    float a = g_apos;
    float carry = g_carry[(b * 64 + c) * HID_ + ch];
    float U = g_uloc[idx] + expf(a * (float)(64 - p)) * carry;
    float den = expm1f(a * (float)(S_ - s)) / expm1f(a);
    float wkv = U / (den + 1e-8f);
    float att = g_r[idx] * (tf[ch] * g_kv[idx] + wkv);
    __half h, l;
    split2h(att, h, l);
    int row = idx >> 10;
    __half* base = g_A2 + (size_t)row * KSP + ch;
    base[0]    = h;
    base[1024] = l;
}

// ---------------------------------------------------------------------------
// launch
// ---------------------------------------------------------------------------
extern "C" void kernel_launch(void* const* d_in, const int* in_sizes, int n_in,
                              void* d_out, int out_size) {
    const float* hidden = (const float*)d_in[0];
    const float* cosb   = (const float*)d_in[1];
    const float* sinb   = (const float*)d_in[2];
    const float* W_rkv  = (const float*)d_in[3];
    const float* W_o    = (const float*)d_in[4];
    const float* tdec   = (const float*)d_in[5];
    const float* tfirst = (const float*)d_in[6];
    const float* tmix   = (const float*)d_in[7];
    float* out = (float*)d_out;

    __half *A2, *B2rkv, *B2o;
    float *rkv;
    cudaGetSymbolAddress((void**)&A2,    g_A2);
    cudaGetSymbolAddress((void**)&B2rkv, g_B2rkv);
    cudaGetSymbolAddress((void**)&B2o,   g_B2o);
    cudaGetSymbolAddress((void**)&rkv,   g_rkv);

    cudaFuncSetAttribute(gemm_hmma,
                         cudaFuncAttributeMaxDynamicSharedMemorySize, SMEM_DYN);

    // (1) scalar decay factor
    prep_kernel<<<1, 256>>>(tdec);
    // (2) token mix + split
    mix_split_kernel<<<(M_ * HID_ / 4 + 255) / 256, 256>>>(hidden, tmix);
    // (3) W_rkv split
    wsplit_kernel<<<(N1_ * HID_ / 4 + 255) / 256, 256>>>(W_rkv, B2rkv, N1_);
    // (4) GEMM1: rkv = mixed @ W_rkv^T
    gemm_hmma<<<dim3(N1_ / BN_T, M_ / BM_T), 128, SMEM_DYN>>>(A2, B2rkv, rkv, N1_);
    // (5) W_o split (independent of GEMM1 result)
    wsplit_kernel<<<(N2_ * HID_ / 4 + 255) / 256, 256>>>(W_o, B2o, N2_);
    // (6) fused rope/sigmoid/kv + local scan
    scanA_kernel<<<(B_ * 64 * HID_) / 256, 256>>>(cosb, sinb);
    // (7) chunk-carry combine
    scanB_kernel<<<(B_ * HID_ + 255) / 256, 256>>>();
    // (8) finalize + gate + split
    scanC_kernel<<<(M_ * HID_ + 255) / 256, 256>>>(tfirst);
    // (9) GEMM2: out = att @ W_o^T
    gemm_hmma<<<dim3(N2_ / BN_T, M_ / BM_T), 128, SMEM_DYN>>>(A2, B2o, out, N2_);
}

// round 13
// speedup vs baseline: 1.5282x; 1.0302x over previous
#include <cuda_runtime.h>
#include <cuda_fp16.h>
#include <stdint.h>
#include <math.h>

// Problem constants
#define B_   2
#define S_   4096
#define HID_ 1024
#define H_   16
#define D_   64
#define M_   (B_*S_)        // 8192
#define N1_  (3*H_*D_)      // 3072
#define N2_  HID_           // 1024
#define KSP  2048           // fp16 2-term split-K': [ah|al] x [bh|bh]

// ---------------------------------------------------------------------------
// Scratch (no cudaMalloc allowed)
// ---------------------------------------------------------------------------
__device__ __align__(256) __half g_A2[(size_t)M_*KSP];        // 33.5 MB
__device__ __align__(256) __half g_B2rkv[(size_t)N1_*KSP];    // 12.6 MB
__device__ __align__(256) __half g_B2o[(size_t)N2_*KSP];      //  4.2 MB
__device__ __align__(256) float g_rkv[(size_t)M_*N1_];        // 100.7 MB
__device__ __align__(256) float g_T[(size_t)B_*64*HID_];      //   0.5 MB
__device__ __align__(256) float g_carry[(size_t)B_*64*HID_];  //   0.5 MB
__device__ float g_gfac;   // exp(a)
__device__ float g_apos;   // a = mean(exp(time_decay)) = -avg_decay

// ---------------------------------------------------------------------------
// helpers
// ---------------------------------------------------------------------------
__device__ __forceinline__ uint32_t smem_u32(const void* p) {
    uint32_t a;
    asm("{ .reg .u64 t; cvta.to.shared.u64 t, %1; cvt.u32.u64 %0, t; }" : "=r"(a) : "l"(p));
    return a;
}
__device__ __forceinline__ void cp16(uint32_t dst, const void* src) {
    asm volatile("cp.async.cg.shared.global [%0], [%1], 16;" :: "r"(dst), "l"(src));
}
__device__ __forceinline__ void ldm_x4(uint32_t* r, uint32_t addr) {
    asm volatile("ldmatrix.sync.aligned.m8n8.x4.shared.b16 {%0,%1,%2,%3}, [%4];"
                 : "=r"(r[0]), "=r"(r[1]), "=r"(r[2]), "=r"(r[3]) : "r"(addr));
}
__device__ __forceinline__ void mma16816(float* c, const uint32_t* a, const uint32_t* b) {
    asm volatile(
        "mma.sync.aligned.m16n8k16.row.col.f32.f16.f16.f32 "
        "{%0,%1,%2,%3}, {%4,%5,%6,%7}, {%8,%9}, {%0,%1,%2,%3};"
        : "+f"(c[0]), "+f"(c[1]), "+f"(c[2]), "+f"(c[3])
        : "r"(a[0]), "r"(a[1]), "r"(a[2]), "r"(a[3]), "r"(b[0]), "r"(b[1]));
}

// ---------------------------------------------------------------------------
// fp16 HMMA GEMM: C[M,N] = A[M,KSP] * B[N,KSP]^T, fp32 out.
// CTA tile 128x128, BK=64, 3-stage cp.async ring, ONE sync per K-tile.
// 4 warps, 64x64 per warp. Fragments double-buffered across k-steps so
// ldsm latency hides behind mma (one exposed ldsm burst per K-tile).
// ---------------------------------------------------------------------------
#define BK 64
#define NKT (KSP/BK)           // 32
#define NSTG 3
#define LDS_ (BK + 8)          // 72
#define BM_T 128
#define BN_T 128
#define A_E (BM_T*LDS_)        // 9216 elems
#define B_E (BN_T*LDS_)        // 9216 elems
#define STG_B ((A_E+B_E)*2)    // 36864 B per stage
#define SMEM_DYN (NSTG*STG_B)  // 110592 B

__global__ void __launch_bounds__(128, 2)
gemm_hmma(const __half* __restrict__ A,
          const __half* __restrict__ Bm,
          float* __restrict__ C, int N) {
    extern __shared__ __half smem[];
    const uint32_t sb = smem_u32(smem);

    const int tid = threadIdx.x;
    const int wid = tid >> 5, lane = tid & 31;
    const int bm = blockIdx.y * BM_T;
    const int bn = blockIdx.x * BN_T;
    const int wm = (wid & 1) * 64;
    const int wn = (wid >> 1) * 64;

    float acc[4][8][4];
    #pragma unroll
    for (int i = 0; i < 4; i++)
        #pragma unroll
        for (int j = 0; j < 8; j++)
            #pragma unroll
            for (int q = 0; q < 4; q++) acc[i][j][q] = 0.f;

    const int a_r = lane & 15, a_k = (lane >> 4) << 3;
    const int b_r = (lane & 7) + ((lane >> 4) << 3), b_k = ((lane >> 3) & 1) << 3;
    // per-warp ldsm base offsets (bytes) within a stage
    const uint32_t aoff = (uint32_t)((wm + a_r) * LDS_ + a_k) * 2;
    const uint32_t boff = (uint32_t)((wn + b_r) * LDS_ + b_k) * 2 + A_E * 2;

    auto load_tile = [&](int kt, int st) {
        const size_t k0 = (size_t)kt * BK;
        uint32_t da = sb + (uint32_t)st * STG_B;
        uint32_t db = da + A_E * 2;
        #pragma unroll
        for (int j = 0; j < 8; j++) {
            int c = tid + j * 128;
            int r = c >> 3, k = (c & 7) * 8;
            cp16(da + (uint32_t)(r * LDS_ + k) * 2,
                 A + (size_t)(bm + r) * KSP + k0 + k);
        }
        #pragma unroll
        for (int j = 0; j < 8; j++) {
            int c = tid + j * 128;
            int r = c >> 3, k = (c & 7) * 8;
            cp16(db + (uint32_t)(r * LDS_ + k) * 2,
                 Bm + (size_t)(bn + r) * KSP + k0 + k);
        }
        asm volatile("cp.async.commit_group;" ::: "memory");
    };

    load_tile(0, 0);
    load_tile(1, 1);

    uint32_t af[2][4][4];   // double-buffered A frags
    uint32_t bf[2][8][2];   // double-buffered B frags

    for (int kt = 0; kt < NKT; kt++) {
        const int st = kt % NSTG;
        if (kt < NKT - 1) asm volatile("cp.async.wait_group 1;" ::: "memory");
        else              asm volatile("cp.async.wait_group 0;" ::: "memory");
        __syncthreads();

        const int nt = kt + NSTG - 1;
        if (nt < NKT) load_tile(nt, nt % NSTG);

        const uint32_t stg = sb + (uint32_t)st * STG_B;

        // prologue: frags for ks=0
        #pragma unroll
        for (int mi = 0; mi < 4; mi++)
            ldm_x4(af[0][mi], stg + aoff + (uint32_t)(mi * 16 * LDS_) * 2);
        #pragma unroll
        for (int p = 0; p < 4; p++) {
            uint32_t r[4];
            ldm_x4(r, stg + boff + (uint32_t)(p * 16 * LDS_) * 2);
            bf[0][p * 2 + 0][0] = r[0]; bf[0][p * 2 + 0][1] = r[1];
            bf[0][p * 2 + 1][0] = r[2]; bf[0][p * 2 + 1][1] = r[3];
        }

        #pragma unroll
        for (int ks = 0; ks < BK / 16; ks++) {
            const int cur = ks & 1, nxt = cur ^ 1;
            if (ks < BK / 16 - 1) {
                const uint32_t kb = (uint32_t)((ks + 1) * 16 * 2);
                #pragma unroll
                for (int mi = 0; mi < 4; mi++)
                    ldm_x4(af[nxt][mi], stg + aoff + (uint32_t)(mi * 16 * LDS_) * 2 + kb);
                #pragma unroll
                for (int p = 0; p < 4; p++) {
                    uint32_t r[4];
                    ldm_x4(r, stg + boff + (uint32_t)(p * 16 * LDS_) * 2 + kb);
                    bf[nxt][p * 2 + 0][0] = r[0]; bf[nxt][p * 2 + 0][1] = r[1];
                    bf[nxt][p * 2 + 1][0] = r[2]; bf[nxt][p * 2 + 1][1] = r[3];
                }
            }
            #pragma unroll
            for (int mi = 0; mi < 4; mi++)
                #pragma unroll
                for (int nj = 0; nj < 8; nj++)
                    mma16816(acc[mi][nj], af[cur][mi], bf[cur][nj]);
        }
    }

    // epilogue
    const int er = lane >> 2, ec = (lane & 3) * 2;
    #pragma unroll
    for (int mi = 0; mi < 4; mi++) {
        #pragma unroll
        for (int nj = 0; nj < 8; nj++) {
            size_t row0 = (size_t)(bm + wm + mi * 16 + er);
            size_t col  = (size_t)(bn + wn + nj * 8 + ec);
            float2 v0 = make_float2(acc[mi][nj][0], acc[mi][nj][1]);
            float2 v1 = make_float2(acc[mi][nj][2], acc[mi][nj][3]);
            *(float2*)(C + row0 * N + col)       = v0;
            *(float2*)(C + (row0 + 8) * N + col) = v1;
        }
    }
}

// ---------------------------------------------------------------------------
// fp16 split helper
// ---------------------------------------------------------------------------
__device__ __forceinline__ void split2h(float x, __half& h, __half& l) {
    h = __float2half_rn(x);
    l = __float2half_rn(x - __half2float(h));
}

// 1) token mix + split -> g_A2 = [ah | al]
__global__ void mix_split_kernel(const float* __restrict__ hsrc,
                                 const float* __restrict__ tm) {
    int i4 = blockIdx.x * blockDim.x + threadIdx.x;
    if (i4 >= M_ * HID_ / 4) return;
    int e = i4 * 4;
    int col = e & (HID_ - 1);
    int row = e >> 10;
    int s = row & (S_ - 1);
    float4 hv = *(const float4*)(hsrc + e);
    float4 tv = *(const float4*)(tm + col);
    float4 pv = make_float4(0.f, 0.f, 0.f, 0.f);
    if (s) pv = *(const float4*)(hsrc + e - HID_);
    float m[4] = { hv.x * tv.x + pv.x * (1.f - tv.x),
                   hv.y * tv.y + pv.y * (1.f - tv.y),
                   hv.z * tv.z + pv.z * (1.f - tv.z),
                   hv.w * tv.w + pv.w * (1.f - tv.w) };
    __half h[4], l[4];
    #pragma unroll
    for (int i = 0; i < 4; i++) split2h(m[i], h[i], l[i]);
    __half* base = g_A2 + (size_t)row * KSP + col;
    *(uint64_t*)(base)        = *(uint64_t*)h;
    *(uint64_t*)(base + 1024) = *(uint64_t*)l;
}

// weight split -> out = [bh | bh]
__global__ void wsplit_kernel(const float* __restrict__ W,
                              __half* __restrict__ out, int rows) {
    int i4 = blockIdx.x * blockDim.x + threadIdx.x;
    if (i4 >= rows * (HID_ / 4)) return;
    int e = i4 * 4;
    int col = e & (HID_ - 1);
    int row = e >> 10;
    float4 w = *(const float4*)(W + e);
    float m[4] = { w.x, w.y, w.z, w.w };
    __half h[4];
    #pragma unroll
    for (int i = 0; i < 4; i++) h[i] = __float2half_rn(m[i]);
    __half* base = out + (size_t)row * KSP + col;
    *(uint64_t*)(base)        = *(uint64_t*)h;
    *(uint64_t*)(base + 1024) = *(uint64_t*)h;
}

// 4) scalar decay factor: a = mean(exp(td)), g = exp(a)
__global__ void prep_kernel(const float* __restrict__ td) {
    __shared__ float red[256];
    float s = 0.f;
    for (int i = threadIdx.x; i < H_ * D_; i += 256) s += expf(td[i]);
    red[threadIdx.x] = s;
    __syncthreads();
    for (int w = 128; w > 0; w >>= 1) {
        if (threadIdx.x < w) red[threadIdx.x] += red[threadIdx.x + w];
        __syncthreads();
    }
    if (threadIdx.x == 0) {
        float a = red[0] / (float)(H_ * D_);
        g_apos = a;
        g_gfac = expf(a);
    }
}

// shared recompute: rope/sigmoid/kv for one (row, ch)
__device__ __forceinline__ void rkv_recompute(
    size_t row, int s, int ch, int pd, int d, float sign,
    const float* __restrict__ cosb, const float* __restrict__ sinb,
    float& rr, float& kvp)
{
    const float* base = g_rkv + row * N1_;
    float rv  = base[ch];
    float rpv = base[pd];
    float kvv = base[1024 + ch];
    float kpv = base[1024 + pd];
    float vv  = base[2048 + ch];
    float cc = cosb[s * 64 + d];
    float sn = sinb[s * 64 + d];
    float rs  = 1.f / (1.f + __expf(-rv));
    float rps = 1.f / (1.f + __expf(-rpv));
    rr  = rs * cc + sign * rps * sn;
    float kk = kvv * cc + sign * kpv * sn;
    kvp = kk * vv;
}

// 5a) pass 1: per-chunk decayed suffix totals only (no bulk writes)
__global__ void scanA_kernel(const float* __restrict__ cosb,
                             const float* __restrict__ sinb) {
    int gid = blockIdx.x * blockDim.x + threadIdx.x;   // B_*64*HID_ = 131072
    int ch = gid & (HID_ - 1);
    int c  = (gid >> 10) & 63;
    int b  = gid >> 16;
    int d  = ch & 63;
    int pd = ch ^ 32;
    float sign = (d < 32) ? -1.f : 1.f;
    float g = g_gfac;

    float u = 0.f;
    #pragma unroll 2
    for (int p = 63; p >= 0; p--) {
        int s = c * 64 + p;
        size_t row = (size_t)b * S_ + s;
        float rr, kvp;
        rkv_recompute(row, s, ch, pd, d, sign, cosb, sinb, rr, kvp);
        u = fmaf(g, u, kvp);
    }
    g_T[gid] = u;
}

// 5b) chunk-carry suffix combine (per channel)
__global__ void scanB_kernel() {
    int t = blockIdx.x * blockDim.x + threadIdx.x;     // B_*HID_ = 2048
    if (t >= B_ * HID_) return;
    int ch = t & (HID_ - 1);
    int b  = t >> 10;
    float gL = expf(g_apos * 64.f);
    float usuf = 0.f;
    for (int c = 63; c >= 0; c--) {
        int i = (b * 64 + c) * HID_ + ch;
        g_carry[i] = usuf;
        usuf = fmaf(gL, usuf, g_T[i]);
    }
}

// 5c) pass 2: recompute local scan + finalize + gate + split -> g_A2
__global__ void scanC_kernel(const float* __restrict__ cosb,
                             const float* __restrict__ sinb,
                             const float* __restrict__ tf) {
    int gid = blockIdx.x * blockDim.x + threadIdx.x;   // B_*64*HID_
    int ch = gid & (HID_ - 1);
    int c  = (gid >> 10) & 63;
    int b  = gid >> 16;
    int d  = ch & 63;
    int pd = ch ^ 32;
    float sign = (d < 32) ? -1.f : 1.f;
    float a = g_apos;
    float g = g_gfac;
    float tfv = tf[ch];
    float carry = g_carry[(b * 64 + c) * HID_ + ch];
    float inv_em1 = 1.f / expm1f(a);

    float u = 0.f;
    #pragma unroll 2
    for (int p = 63; p >= 0; p--) {
        int s = c * 64 + p;
        size_t row = (size_t)b * S_ + s;
        float rr, kvp;
        rkv_recompute(row, s, ch, pd, d, sign, cosb, sinb, rr, kvp);
        u = fmaf(g, u, kvp);   // == uloc[p]
        float U = u + expf(a * (float)(64 - p)) * carry;
        float den = expm1f(a * (float)(S_ - s)) * inv_em1;
        float wkv = U / (den + 1e-8f);
        float att = rr * (tfv * kvp + wkv);
        __half hh, ll;
        split2h(att, hh, ll);
        __half* basew = g_A2 + row * KSP + ch;
        basew[0]    = hh;
        basew[1024] = ll;
    }
}

// ---------------------------------------------------------------------------
// launch
// ---------------------------------------------------------------------------
extern "C" void kernel_launch(void* const* d_in, const int* in_sizes, int n_in,
                              void* d_out, int out_size) {
    const float* hidden = (const float*)d_in[0];
    const float* cosb   = (const float*)d_in[1];
    const float* sinb   = (const float*)d_in[2];
    const float* W_rkv  = (const float*)d_in[3];
    const float* W_o    = (const float*)d_in[4];
    const float* tdec   = (const float*)d_in[5];
    const float* tfirst = (const float*)d_in[6];
    const float* tmix   = (const float*)d_in[7];
    float* out = (float*)d_out;

    __half *A2, *B2rkv, *B2o;
    float *rkv;
    cudaGetSymbolAddress((void**)&A2,    g_A2);
    cudaGetSymbolAddress((void**)&B2rkv, g_B2rkv);
    cudaGetSymbolAddress((void**)&B2o,   g_B2o);
    cudaGetSymbolAddress((void**)&rkv,   g_rkv);

    cudaFuncSetAttribute(gemm_hmma,
                         cudaFuncAttributeMaxDynamicSharedMemorySize, SMEM_DYN);

    // (1) scalar decay factor
    prep_kernel<<<1, 256>>>(tdec);
    // (2) token mix + split
    mix_split_kernel<<<(M_ * HID_ / 4 + 255) / 256, 256>>>(hidden, tmix);
    // (3) W_rkv split
    wsplit_kernel<<<(N1_ * HID_ / 4 + 255) / 256, 256>>>(W_rkv, B2rkv, N1_);
    // (4) GEMM1: rkv = mixed @ W_rkv^T
    gemm_hmma<<<dim3(N1_ / BN_T, M_ / BM_T), 128, SMEM_DYN>>>(A2, B2rkv, rkv, N1_);
    // (5) W_o split (independent of GEMM1 result)
    wsplit_kernel<<<(N2_ * HID_ / 4 + 255) / 256, 256>>>(W_o, B2o, N2_);
    // (6) pass 1: chunk totals
    scanA_kernel<<<(B_ * 64 * HID_) / 256, 256>>>(cosb, sinb);
    // (7) chunk-carry combine
    scanB_kernel<<<(B_ * HID_ + 255) / 256, 256>>>();
    // (8) pass 2: recompute + finalize + gate + split
    scanC_kernel<<<(B_ * 64 * HID_) / 256, 256>>>(cosb, sinb, tfirst);
    // (9) GEMM2: out = att @ W_o^T
    gemm_hmma<<<dim3(N2_ / BN_T, M_ / BM_T), 128, SMEM_DYN>>>(A2, B2o, out, N2_);
}

// round 14
// speedup vs baseline: 1.6972x; 1.1106x over previous
#include <cuda_runtime.h>
#include <cuda_fp16.h>
#include <stdint.h>
#include <math.h>

// Problem constants
#define B_   2
#define S_   4096
#define HID_ 1024
#define H_   16
#define D_   64
#define M_   (B_*S_)        // 8192
#define N1_  (3*H_*D_)      // 3072
#define N2_  HID_           // 1024
#define KSP  2048           // fp16 2-term split-K': [ah|al] x [bh|bh]

// ---------------------------------------------------------------------------
// Scratch (no cudaMalloc allowed)
// ---------------------------------------------------------------------------
__device__ __align__(256) __half g_A2[(size_t)M_*KSP];        // 33.5 MB
__device__ __align__(256) __half g_B2rkv[(size_t)N1_*KSP];    // 12.6 MB
__device__ __align__(256) __half g_B2o[(size_t)N2_*KSP];      //  4.2 MB
__device__ __align__(256) float g_rkv[(size_t)M_*N1_];        // 100.7 MB
__device__ __align__(256) float g_T[(size_t)B_*64*HID_];      //   0.5 MB
__device__ __align__(256) float g_carry[(size_t)B_*64*HID_];  //   0.5 MB
__device__ float g_gfac;   // exp(a)
__device__ float g_apos;   // a = mean(exp(time_decay)) = -avg_decay

// ---------------------------------------------------------------------------
// helpers
// ---------------------------------------------------------------------------
__device__ __forceinline__ uint32_t smem_u32(const void* p) {
    uint32_t a;
    asm("{ .reg .u64 t; cvta.to.shared.u64 t, %1; cvt.u32.u64 %0, t; }" : "=r"(a) : "l"(p));
    return a;
}
__device__ __forceinline__ void cp16(uint32_t dst, const void* src) {
    asm volatile("cp.async.cg.shared.global [%0], [%1], 16;" :: "r"(dst), "l"(src));
}
__device__ __forceinline__ void ldm_x4(uint32_t* r, uint32_t addr) {
    asm volatile("ldmatrix.sync.aligned.m8n8.x4.shared.b16 {%0,%1,%2,%3}, [%4];"
                 : "=r"(r[0]), "=r"(r[1]), "=r"(r[2]), "=r"(r[3]) : "r"(addr));
}
__device__ __forceinline__ void mma16816(float* c, const uint32_t* a, const uint32_t* b) {
    asm volatile(
        "mma.sync.aligned.m16n8k16.row.col.f32.f16.f16.f32 "
        "{%0,%1,%2,%3}, {%4,%5,%6,%7}, {%8,%9}, {%0,%1,%2,%3};"
        : "+f"(c[0]), "+f"(c[1]), "+f"(c[2]), "+f"(c[3])
        : "r"(a[0]), "r"(a[1]), "r"(a[2]), "r"(a[3]), "r"(b[0]), "r"(b[1]));
}

// ---------------------------------------------------------------------------
// fp16 HMMA GEMM: C[:, nb0:nb0+gridN] = A[M,K] * B[nb0.., K]^T, fp32 out.
// A,B rows strided KSP; runtime K (1024 = high-term only, 2048 = 2-term).
// CTA tile 128x128, BK=64, 3-stage cp.async ring, ONE sync per K-tile.
// 4 warps, 64x64 per warp; frags double-buffered across k-steps.
// ---------------------------------------------------------------------------
#define BK 64
#define NSTG 3
#define LDS_ (BK + 8)          // 72
#define BM_T 128
#define BN_T 128
#define A_E (BM_T*LDS_)        // 9216 elems
#define B_E (BN_T*LDS_)        // 9216 elems
#define STG_B ((A_E+B_E)*2)    // 36864 B per stage
#define SMEM_DYN (NSTG*STG_B)  // 110592 B

__global__ void __launch_bounds__(128, 2)
gemm_hmma(const __half* __restrict__ A,
          const __half* __restrict__ Bm,
          float* __restrict__ C, int N, int K, int nb0) {
    extern __shared__ __half smem[];
    const uint32_t sb = smem_u32(smem);
    const int nkt = K >> 6;

    const int tid = threadIdx.x;
    const int wid = tid >> 5, lane = tid & 31;
    const int bm = blockIdx.y * BM_T;
    const int bn = nb0 + blockIdx.x * BN_T;
    const int wm = (wid & 1) * 64;
    const int wn = (wid >> 1) * 64;

    float acc[4][8][4];
    #pragma unroll
    for (int i = 0; i < 4; i++)
        #pragma unroll
        for (int j = 0; j < 8; j++)
            #pragma unroll
            for (int q = 0; q < 4; q++) acc[i][j][q] = 0.f;

    const int a_r = lane & 15, a_k = (lane >> 4) << 3;
    const int b_r = (lane & 7) + ((lane >> 4) << 3), b_k = ((lane >> 3) & 1) << 3;
    const uint32_t aoff = (uint32_t)((wm + a_r) * LDS_ + a_k) * 2;
    const uint32_t boff = (uint32_t)((wn + b_r) * LDS_ + b_k) * 2 + A_E * 2;

    auto load_tile = [&](int kt, int st) {
        const size_t k0 = (size_t)kt * BK;
        uint32_t da = sb + (uint32_t)st * STG_B;
        uint32_t db = da + A_E * 2;
        #pragma unroll
        for (int j = 0; j < 8; j++) {
            int c = tid + j * 128;
            int r = c >> 3, k = (c & 7) * 8;
            cp16(da + (uint32_t)(r * LDS_ + k) * 2,
                 A + (size_t)(bm + r) * KSP + k0 + k);
        }
        #pragma unroll
        for (int j = 0; j < 8; j++) {
            int c = tid + j * 128;
            int r = c >> 3, k = (c & 7) * 8;
            cp16(db + (uint32_t)(r * LDS_ + k) * 2,
                 Bm + (size_t)(bn + r) * KSP + k0 + k);
        }
        asm volatile("cp.async.commit_group;" ::: "memory");
    };

    load_tile(0, 0);
    load_tile(1, 1);

    uint32_t af[2][4][4];
    uint32_t bf[2][8][2];

    for (int kt = 0; kt < nkt; kt++) {
        const int st = kt % NSTG;
        if (kt < nkt - 1) asm volatile("cp.async.wait_group 1;" ::: "memory");
        else              asm volatile("cp.async.wait_group 0;" ::: "memory");
        __syncthreads();

        const int nt = kt + NSTG - 1;
        if (nt < nkt) load_tile(nt, nt % NSTG);

        const uint32_t stg = sb + (uint32_t)st * STG_B;

        #pragma unroll
        for (int mi = 0; mi < 4; mi++)
            ldm_x4(af[0][mi], stg + aoff + (uint32_t)(mi * 16 * LDS_) * 2);
        #pragma unroll
        for (int p = 0; p < 4; p++) {
            uint32_t r[4];
            ldm_x4(r, stg + boff + (uint32_t)(p * 16 * LDS_) * 2);
            bf[0][p * 2 + 0][0] = r[0]; bf[0][p * 2 + 0][1] = r[1];
            bf[0][p * 2 + 1][0] = r[2]; bf[0][p * 2 + 1][1] = r[3];
        }

        #pragma unroll
        for (int ks = 0; ks < BK / 16; ks++) {
            const int cur = ks & 1, nxt = cur ^ 1;
            if (ks < BK / 16 - 1) {
                const uint32_t kb = (uint32_t)((ks + 1) * 16 * 2);
                #pragma unroll
                for (int mi = 0; mi < 4; mi++)
                    ldm_x4(af[nxt][mi], stg + aoff + (uint32_t)(mi * 16 * LDS_) * 2 + kb);
                #pragma unroll
                for (int p = 0; p < 4; p++) {
                    uint32_t r[4];
                    ldm_x4(r, stg + boff + (uint32_t)(p * 16 * LDS_) * 2 + kb);
                    bf[nxt][p * 2 + 0][0] = r[0]; bf[nxt][p * 2 + 0][1] = r[1];
                    bf[nxt][p * 2 + 1][0] = r[2]; bf[nxt][p * 2 + 1][1] = r[3];
                }
            }
            #pragma unroll
            for (int mi = 0; mi < 4; mi++)
                #pragma unroll
                for (int nj = 0; nj < 8; nj++)
                    mma16816(acc[mi][nj], af[cur][mi], bf[cur][nj]);
        }
    }

    // epilogue
    const int er = lane >> 2, ec = (lane & 3) * 2;
    #pragma unroll
    for (int mi = 0; mi < 4; mi++) {
        #pragma unroll
        for (int nj = 0; nj < 8; nj++) {
            size_t row0 = (size_t)(bm + wm + mi * 16 + er);
            size_t col  = (size_t)(bn + wn + nj * 8 + ec);
            float2 v0 = make_float2(acc[mi][nj][0], acc[mi][nj][1]);
            float2 v1 = make_float2(acc[mi][nj][2], acc[mi][nj][3]);
            *(float2*)(C + row0 * N + col)       = v0;
            *(float2*)(C + (row0 + 8) * N + col) = v1;
        }
    }
}

// ---------------------------------------------------------------------------
// fp16 split helper
// ---------------------------------------------------------------------------
__device__ __forceinline__ void split2h(float x, __half& h, __half& l) {
    h = __float2half_rn(x);
    l = __float2half_rn(x - __half2float(h));
}

// 1) token mix + split -> g_A2 = [ah | al]
__global__ void mix_split_kernel(const float* __restrict__ hsrc,
                                 const float* __restrict__ tm) {
    int i4 = blockIdx.x * blockDim.x + threadIdx.x;
    if (i4 >= M_ * HID_ / 4) return;
    int e = i4 * 4;
    int col = e & (HID_ - 1);
    int row = e >> 10;
    int s = row & (S_ - 1);
    float4 hv = *(const float4*)(hsrc + e);
    float4 tv = *(const float4*)(tm + col);
    float4 pv = make_float4(0.f, 0.f, 0.f, 0.f);
    if (s) pv = *(const float4*)(hsrc + e - HID_);
    float m[4] = { hv.x * tv.x + pv.x * (1.f - tv.x),
                   hv.y * tv.y + pv.y * (1.f - tv.y),
                   hv.z * tv.z + pv.z * (1.f - tv.z),
                   hv.w * tv.w + pv.w * (1.f - tv.w) };
    __half h[4], l[4];
    #pragma unroll
    for (int i = 0; i < 4; i++) split2h(m[i], h[i], l[i]);
    __half* base = g_A2 + (size_t)row * KSP + col;
    *(uint64_t*)(base)        = *(uint64_t*)h;
    *(uint64_t*)(base + 1024) = *(uint64_t*)l;
}

// weight split -> out = [bh | bh]
__global__ void wsplit_kernel(const float* __restrict__ W,
                              __half* __restrict__ out, int rows) {
    int i4 = blockIdx.x * blockDim.x + threadIdx.x;
    if (i4 >= rows * (HID_ / 4)) return;
    int e = i4 * 4;
    int col = e & (HID_ - 1);
    int row = e >> 10;
    float4 w = *(const float4*)(W + e);
    float m[4] = { w.x, w.y, w.z, w.w };
    __half h[4];
    #pragma unroll
    for (int i = 0; i < 4; i++) h[i] = __float2half_rn(m[i]);
    __half* base = out + (size_t)row * KSP + col;
    *(uint64_t*)(base)        = *(uint64_t*)h;
    *(uint64_t*)(base + 1024) = *(uint64_t*)h;
}

// 4) scalar decay factor: a = mean(exp(td)), g = exp(a)
__global__ void prep_kernel(const float* __restrict__ td) {
    __shared__ float red[256];
    float s = 0.f;
    for (int i = threadIdx.x; i < H_ * D_; i += 256) s += expf(td[i]);
    red[threadIdx.x] = s;
    __syncthreads();
    for (int w = 128; w > 0; w >>= 1) {
        if (threadIdx.x < w) red[threadIdx.x] += red[threadIdx.x + w];
        __syncthreads();
    }
    if (threadIdx.x == 0) {
        float a = red[0] / (float)(H_ * D_);
        g_apos = a;
        g_gfac = expf(a);
    }
}

// kv-only recompute (scanA doesn't need r)
__device__ __forceinline__ float kv_recompute(
    size_t row, int s, int ch, int pd, int d, float sign,
    const float* __restrict__ cosb, const float* __restrict__ sinb)
{
    const float* base = g_rkv + row * N1_;
    float kvv = base[1024 + ch];
    float kpv = base[1024 + pd];
    float vv  = base[2048 + ch];
    float cc = cosb[s * 64 + d];
    float sn = sinb[s * 64 + d];
    float kk = kvv * cc + sign * kpv * sn;
    return kk * vv;
}

// full recompute (scanC needs r too)
__device__ __forceinline__ void rkv_recompute(
    size_t row, int s, int ch, int pd, int d, float sign,
    const float* __restrict__ cosb, const float* __restrict__ sinb,
    float& rr, float& kvp)
{
    const float* base = g_rkv + row * N1_;
    float rv  = base[ch];
    float rpv = base[pd];
    float kvv = base[1024 + ch];
    float kpv = base[1024 + pd];
    float vv  = base[2048 + ch];
    float cc = cosb[s * 64 + d];
    float sn = sinb[s * 64 + d];
    float rs  = 1.f / (1.f + __expf(-rv));
    float rps = 1.f / (1.f + __expf(-rpv));
    rr  = rs * cc + sign * rps * sn;
    float kk = kvv * cc + sign * kpv * sn;
    kvp = kk * vv;
}

// 5a) pass 1: per-chunk decayed suffix totals only (k/v reads only)
__global__ void scanA_kernel(const float* __restrict__ cosb,
                             const float* __restrict__ sinb) {
    int gid = blockIdx.x * blockDim.x + threadIdx.x;   // B_*64*HID_ = 131072
    int ch = gid & (HID_ - 1);
    int c  = (gid >> 10) & 63;
    int b  = gid >> 16;
    int d  = ch & 63;
    int pd = ch ^ 32;
    float sign = (d < 32) ? -1.f : 1.f;
    float g = g_gfac;

    float u = 0.f;
    #pragma unroll 2
    for (int p = 63; p >= 0; p--) {
        int s = c * 64 + p;
        size_t row = (size_t)b * S_ + s;
        float kvp = kv_recompute(row, s, ch, pd, d, sign, cosb, sinb);
        u = fmaf(g, u, kvp);
    }
    g_T[gid] = u;
}

// 5b) chunk-carry suffix combine (per channel)
__global__ void scanB_kernel() {
    int t = blockIdx.x * blockDim.x + threadIdx.x;     // B_*HID_ = 2048
    if (t >= B_ * HID_) return;
    int ch = t & (HID_ - 1);
    int b  = t >> 10;
    float gL = expf(g_apos * 64.f);
    float usuf = 0.f;
    for (int c = 63; c >= 0; c--) {
        int i = (b * 64 + c) * HID_ + ch;
        g_carry[i] = usuf;
        usuf = fmaf(gL, usuf, g_T[i]);
    }
}

// 5c) pass 2: recompute local scan + finalize + gate + split -> g_A2
__global__ void scanC_kernel(const float* __restrict__ cosb,
                             const float* __restrict__ sinb,
                             const float* __restrict__ tf) {
    int gid = blockIdx.x * blockDim.x + threadIdx.x;   // B_*64*HID_
    int ch = gid & (HID_ - 1);
    int c  = (gid >> 10) & 63;
    int b  = gid >> 16;
    int d  = ch & 63;
    int pd = ch ^ 32;
    float sign = (d < 32) ? -1.f : 1.f;
    float a = g_apos;
    float g = g_gfac;
    float tfv = tf[ch];
    float carry = g_carry[(b * 64 + c) * HID_ + ch];
    float inv_em1 = 1.f / expm1f(a);

    float u = 0.f;
    #pragma unroll 2
    for (int p = 63; p >= 0; p--) {
        int s = c * 64 + p;
        size_t row = (size_t)b * S_ + s;
        float rr, kvp;
        rkv_recompute(row, s, ch, pd, d, sign, cosb, sinb, rr, kvp);
        u = fmaf(g, u, kvp);   // == uloc[p]
        float U = u + expf(a * (float)(64 - p)) * carry;
        float den = expm1f(a * (float)(S_ - s)) * inv_em1;
        float wkv = U / (den + 1e-8f);
        float att = rr * (tfv * kvp + wkv);
        __half hh, ll;
        split2h(att, hh, ll);
        __half* basew = g_A2 + row * KSP + ch;
        basew[0]    = hh;
        basew[1024] = ll;
    }
}

// ---------------------------------------------------------------------------
// launch
// ---------------------------------------------------------------------------
extern "C" void kernel_launch(void* const* d_in, const int* in_sizes, int n_in,
                              void* d_out, int out_size) {
    const float* hidden = (const float*)d_in[0];
    const float* cosb   = (const float*)d_in[1];
    const float* sinb   = (const float*)d_in[2];
    const float* W_rkv  = (const float*)d_in[3];
    const float* W_o    = (const float*)d_in[4];
    const float* tdec   = (const float*)d_in[5];
    const float* tfirst = (const float*)d_in[6];
    const float* tmix   = (const float*)d_in[7];
    float* out = (float*)d_out;

    __half *A2, *B2rkv, *B2o;
    float *rkv;
    cudaGetSymbolAddress((void**)&A2,    g_A2);
    cudaGetSymbolAddress((void**)&B2rkv, g_B2rkv);
    cudaGetSymbolAddress((void**)&B2o,   g_B2o);
    cudaGetSymbolAddress((void**)&rkv,   g_rkv);

    cudaFuncSetAttribute(gemm_hmma,
                         cudaFuncAttributeMaxDynamicSharedMemorySize, SMEM_DYN);

    // (1) scalar decay factor
    prep_kernel<<<1, 256>>>(tdec);
    // (2) token mix + split
    mix_split_kernel<<<(M_ * HID_ / 4 + 255) / 256, 256>>>(hidden, tmix);
    // (3) W_rkv split
    wsplit_kernel<<<(N1_ * HID_ / 4 + 255) / 256, 256>>>(W_rkv, B2rkv, N1_);
    // (4a) GEMM1 r-section: cols [0,1024), high-term only (K=1024)
    gemm_hmma<<<dim3(1024 / BN_T, M_ / BM_T), 128, SMEM_DYN>>>(
        A2, B2rkv, rkv, N1_, 1024, 0);
    // (4b) GEMM1 k/v-section: cols [1024,3072), 2-term (K=2048)
    gemm_hmma<<<dim3(2048 / BN_T, M_ / BM_T), 128, SMEM_DYN>>>(
        A2, B2rkv, rkv, N1_, 2048, 1024);
    // (5) W_o split
    wsplit_kernel<<<(N2_ * HID_ / 4 + 255) / 256, 256>>>(W_o, B2o, N2_);
    // (6) pass 1: chunk totals (k/v only)
    scanA_kernel<<<(B_ * 64 * HID_) / 256, 256>>>(cosb, sinb);
    // (7) chunk-carry combine
    scanB_kernel<<<(B_ * HID_ + 255) / 256, 256>>>();
    // (8) pass 2: recompute + finalize + gate + split
    scanC_kernel<<<(B_ * 64 * HID_) / 256, 256>>>(cosb, sinb, tfirst);
    // (9) GEMM2: out = att @ W_o^T (2-term, K=2048)
    gemm_hmma<<<dim3(N2_ / BN_T, M_ / BM_T), 128, SMEM_DYN>>>(
        A2, B2o, out, N2_, 2048, 0);
}

// round 15
// speedup vs baseline: 1.9251x; 1.1343x over previous
#include <cuda_runtime.h>
#include <cuda_fp16.h>
#include <stdint.h>
#include <math.h>

// Problem constants
#define B_   2
#define S_   4096
#define HID_ 1024
#define H_   16
#define D_   64
#define M_   (B_*S_)        // 8192
#define N1_  (3*H_*D_)      // 3072
#define N2_  HID_           // 1024
#define KSP  2048           // fp16 2-term split-K': [ah|al] x [bh|bh]

// ---------------------------------------------------------------------------
// Scratch (no cudaMalloc allowed)
// ---------------------------------------------------------------------------
__device__ __align__(256) __half g_A2[(size_t)M_*KSP];        // 33.5 MB
__device__ __align__(256) __half g_B2rkv[(size_t)N1_*KSP];    // 12.6 MB
__device__ __align__(256) __half g_B2o[(size_t)N2_*KSP];      //  4.2 MB
__device__ __align__(256) float g_rkv[(size_t)M_*N1_];        // 100.7 MB
__device__ __align__(256) float g_T[(size_t)B_*64*HID_];      //   0.5 MB
__device__ __align__(256) float g_carry[(size_t)B_*64*HID_];  //   0.5 MB
__device__ float g_gfac;   // exp(a)
__device__ float g_apos;   // a = mean(exp(time_decay)) = -avg_decay

// ---------------------------------------------------------------------------
// helpers
// ---------------------------------------------------------------------------
__device__ __forceinline__ uint32_t smem_u32(const void* p) {
    uint32_t a;
    asm("{ .reg .u64 t; cvta.to.shared.u64 t, %1; cvt.u32.u64 %0, t; }" : "=r"(a) : "l"(p));
    return a;
}
__device__ __forceinline__ void cp16(uint32_t dst, const void* src) {
    asm volatile("cp.async.cg.shared.global [%0], [%1], 16;" :: "r"(dst), "l"(src));
}
__device__ __forceinline__ void ldm_x4(uint32_t* r, uint32_t addr) {
    asm volatile("ldmatrix.sync.aligned.m8n8.x4.shared.b16 {%0,%1,%2,%3}, [%4];"
                 : "=r"(r[0]), "=r"(r[1]), "=r"(r[2]), "=r"(r[3]) : "r"(addr));
}
__device__ __forceinline__ void mma16816(float* c, const uint32_t* a, const uint32_t* b) {
    asm volatile(
        "mma.sync.aligned.m16n8k16.row.col.f32.f16.f16.f32 "
        "{%0,%1,%2,%3}, {%4,%5,%6,%7}, {%8,%9}, {%0,%1,%2,%3};"
        : "+f"(c[0]), "+f"(c[1]), "+f"(c[2]), "+f"(c[3])
        : "r"(a[0]), "r"(a[1]), "r"(a[2]), "r"(a[3]), "r"(b[0]), "r"(b[1]));
}

// ---------------------------------------------------------------------------
// fp16 HMMA GEMM. K==0 => merged GEMM1 mapping:
//   blockIdx.x <  16 : kv cols (bn = 1024 + x*128), K = 2048 (2-term)
//   blockIdx.x >= 16 : r  cols (bn = (x-16)*128),   K = 1024 (high only)
// else: bn = nb0 + x*128, runtime K.
// CTA tile 128x128, BK=64, 3-stage cp.async ring, one sync per K-tile.
// 4 warps, 64x64/warp, frag double-buffering.
// ---------------------------------------------------------------------------
#define BK 64
#define NSTG 3
#define LDS_ (BK + 8)          // 72
#define BM_T 128
#define BN_T 128
#define A_E (BM_T*LDS_)        // 9216 elems
#define B_E (BN_T*LDS_)        // 9216 elems
#define STG_B ((A_E+B_E)*2)    // 36864 B per stage
#define SMEM_DYN (NSTG*STG_B)  // 110592 B

__global__ void __launch_bounds__(128, 2)
gemm_hmma(const __half* __restrict__ A,
          const __half* __restrict__ Bm,
          float* __restrict__ C, int N, int K, int nb0) {
    extern __shared__ __half smem[];
    const uint32_t sb = smem_u32(smem);

    int bn, kdim;
    if (K == 0) {
        if (blockIdx.x < 16) { bn = 1024 + blockIdx.x * BN_T; kdim = 2048; }
        else                 { bn = (blockIdx.x - 16) * BN_T; kdim = 1024; }
    } else {
        bn = nb0 + blockIdx.x * BN_T;
        kdim = K;
    }
    const int nkt = kdim >> 6;

    const int tid = threadIdx.x;
    const int wid = tid >> 5, lane = tid & 31;
    const int bm = blockIdx.y * BM_T;
    const int wm = (wid & 1) * 64;
    const int wn = (wid >> 1) * 64;

    float acc[4][8][4];
    #pragma unroll
    for (int i = 0; i < 4; i++)
        #pragma unroll
        for (int j = 0; j < 8; j++)
            #pragma unroll
            for (int q = 0; q < 4; q++) acc[i][j][q] = 0.f;

    const int a_r = lane & 15, a_k = (lane >> 4) << 3;
    const int b_r = (lane & 7) + ((lane >> 4) << 3), b_k = ((lane >> 3) & 1) << 3;
    const uint32_t aoff = (uint32_t)((wm + a_r) * LDS_ + a_k) * 2;
    const uint32_t boff = (uint32_t)((wn + b_r) * LDS_ + b_k) * 2 + A_E * 2;

    auto load_tile = [&](int kt, int st) {
        const size_t k0 = (size_t)kt * BK;
        uint32_t da = sb + (uint32_t)st * STG_B;
        uint32_t db = da + A_E * 2;
        #pragma unroll
        for (int j = 0; j < 8; j++) {
            int c = tid + j * 128;
            int r = c >> 3, k = (c & 7) * 8;
            cp16(da + (uint32_t)(r * LDS_ + k) * 2,
                 A + (size_t)(bm + r) * KSP + k0 + k);
        }
        #pragma unroll
        for (int j = 0; j < 8; j++) {
            int c = tid + j * 128;
            int r = c >> 3, k = (c & 7) * 8;
            cp16(db + (uint32_t)(r * LDS_ + k) * 2,
                 Bm + (size_t)(bn + r) * KSP + k0 + k);
        }
        asm volatile("cp.async.commit_group;" ::: "memory");
    };

    load_tile(0, 0);
    load_tile(1, 1);

    uint32_t af[2][4][4];
    uint32_t bf[2][8][2];

    for (int kt = 0; kt < nkt; kt++) {
        const int st = kt % NSTG;
        if (kt < nkt - 1) asm volatile("cp.async.wait_group 1;" ::: "memory");
        else              asm volatile("cp.async.wait_group 0;" ::: "memory");
        __syncthreads();

        const int nt = kt + NSTG - 1;
        if (nt < nkt) load_tile(nt, nt % NSTG);

        const uint32_t stg = sb + (uint32_t)st * STG_B;

        #pragma unroll
        for (int mi = 0; mi < 4; mi++)
            ldm_x4(af[0][mi], stg + aoff + (uint32_t)(mi * 16 * LDS_) * 2);
        #pragma unroll
        for (int p = 0; p < 4; p++) {
            uint32_t r[4];
            ldm_x4(r, stg + boff + (uint32_t)(p * 16 * LDS_) * 2);
            bf[0][p * 2 + 0][0] = r[0]; bf[0][p * 2 + 0][1] = r[1];
            bf[0][p * 2 + 1][0] = r[2]; bf[0][p * 2 + 1][1] = r[3];
        }

        #pragma unroll
        for (int ks = 0; ks < BK / 16; ks++) {
            const int cur = ks & 1, nxt = cur ^ 1;
            if (ks < BK / 16 - 1) {
                const uint32_t kb = (uint32_t)((ks + 1) * 16 * 2);
                #pragma unroll
                for (int mi = 0; mi < 4; mi++)
                    ldm_x4(af[nxt][mi], stg + aoff + (uint32_t)(mi * 16 * LDS_) * 2 + kb);
                #pragma unroll
                for (int p = 0; p < 4; p++) {
                    uint32_t r[4];
                    ldm_x4(r, stg + boff + (uint32_t)(p * 16 * LDS_) * 2 + kb);
                    bf[nxt][p * 2 + 0][0] = r[0]; bf[nxt][p * 2 + 0][1] = r[1];
                    bf[nxt][p * 2 + 1][0] = r[2]; bf[nxt][p * 2 + 1][1] = r[3];
                }
            }
            #pragma unroll
            for (int mi = 0; mi < 4; mi++)
                #pragma unroll
                for (int nj = 0; nj < 8; nj++)
                    mma16816(acc[mi][nj], af[cur][mi], bf[cur][nj]);
        }
    }

    // epilogue
    const int er = lane >> 2, ec = (lane & 3) * 2;
    #pragma unroll
    for (int mi = 0; mi < 4; mi++) {
        #pragma unroll
        for (int nj = 0; nj < 8; nj++) {
            size_t row0 = (size_t)(bm + wm + mi * 16 + er);
            size_t col  = (size_t)(bn + wn + nj * 8 + ec);
            float2 v0 = make_float2(acc[mi][nj][0], acc[mi][nj][1]);
            float2 v1 = make_float2(acc[mi][nj][2], acc[mi][nj][3]);
            *(float2*)(C + row0 * N + col)       = v0;
            *(float2*)(C + (row0 + 8) * N + col) = v1;
        }
    }
}

// ---------------------------------------------------------------------------
// fp16 split helper
// ---------------------------------------------------------------------------
__device__ __forceinline__ void split2h(float x, __half& h, __half& l) {
    h = __float2half_rn(x);
    l = __float2half_rn(x - __half2float(h));
}

// 1) token mix + split -> g_A2 = [ah | al]
__global__ void mix_split_kernel(const float* __restrict__ hsrc,
                                 const float* __restrict__ tm) {
    int i4 = blockIdx.x * blockDim.x + threadIdx.x;
    if (i4 >= M_ * HID_ / 4) return;
    int e = i4 * 4;
    int col = e & (HID_ - 1);
    int row = e >> 10;
    int s = row & (S_ - 1);
    float4 hv = *(const float4*)(hsrc + e);
    float4 tv = *(const float4*)(tm + col);
    float4 pv = make_float4(0.f, 0.f, 0.f, 0.f);
    if (s) pv = *(const float4*)(hsrc + e - HID_);
    float m[4] = { hv.x * tv.x + pv.x * (1.f - tv.x),
                   hv.y * tv.y + pv.y * (1.f - tv.y),
                   hv.z * tv.z + pv.z * (1.f - tv.z),
                   hv.w * tv.w + pv.w * (1.f - tv.w) };
    __half h[4], l[4];
    #pragma unroll
    for (int i = 0; i < 4; i++) split2h(m[i], h[i], l[i]);
    __half* base = g_A2 + (size_t)row * KSP + col;
    *(uint64_t*)(base)        = *(uint64_t*)h;
    *(uint64_t*)(base + 1024) = *(uint64_t*)l;
}

// weight split -> out = [bh | bh]
__global__ void wsplit_kernel(const float* __restrict__ W,
                              __half* __restrict__ out, int rows) {
    int i4 = blockIdx.x * blockDim.x + threadIdx.x;
    if (i4 >= rows * (HID_ / 4)) return;
    int e = i4 * 4;
    int col = e & (HID_ - 1);
    int row = e >> 10;
    float4 w = *(const float4*)(W + e);
    float m[4] = { w.x, w.y, w.z, w.w };
    __half h[4];
    #pragma unroll
    for (int i = 0; i < 4; i++) h[i] = __float2half_rn(m[i]);
    __half* base = out + (size_t)row * KSP + col;
    *(uint64_t*)(base)        = *(uint64_t*)h;
    *(uint64_t*)(base + 1024) = *(uint64_t*)h;
}

// 4) scalar decay factor: a = mean(exp(td)), g = exp(a)
__global__ void prep_kernel(const float* __restrict__ td) {
    __shared__ float red[256];
    float s = 0.f;
    for (int i = threadIdx.x; i < H_ * D_; i += 256) s += expf(td[i]);
    red[threadIdx.x] = s;
    __syncthreads();
    for (int w = 128; w > 0; w >>= 1) {
        if (threadIdx.x < w) red[threadIdx.x] += red[threadIdx.x + w];
        __syncthreads();
    }
    if (threadIdx.x == 0) {
        float a = red[0] / (float)(H_ * D_);
        g_apos = a;
        g_gfac = expf(a);
    }
}

// kv-only recompute
__device__ __forceinline__ float kv_recompute(
    size_t row, int s, int ch, int pd, int d, float sign,
    const float* __restrict__ cosb, const float* __restrict__ sinb)
{
    const float* base = g_rkv + row * N1_;
    float kvv = base[1024 + ch];
    float kpv = base[1024 + pd];
    float vv  = base[2048 + ch];
    float cc = cosb[s * 64 + d];
    float sn = sinb[s * 64 + d];
    float kk = kvv * cc + sign * kpv * sn;
    return kk * vv;
}

// full recompute
__device__ __forceinline__ void rkv_recompute(
    size_t row, int s, int ch, int pd, int d, float sign,
    const float* __restrict__ cosb, const float* __restrict__ sinb,
    float& rr, float& kvp)
{
    const float* base = g_rkv + row * N1_;
    float rv  = base[ch];
    float rpv = base[pd];
    float kvv = base[1024 + ch];
    float kpv = base[1024 + pd];
    float vv  = base[2048 + ch];
    float cc = cosb[s * 64 + d];
    float sn = sinb[s * 64 + d];
    float rs  = 1.f / (1.f + __expf(-rv));
    float rps = 1.f / (1.f + __expf(-rpv));
    rr  = rs * cc + sign * rps * sn;
    float kk = kvv * cc + sign * kpv * sn;
    kvp = kk * vv;
}

// 5a) pass 1: per-chunk decayed suffix totals only (k/v reads only)
__global__ void scanA_kernel(const float* __restrict__ cosb,
                             const float* __restrict__ sinb) {
    int gid = blockIdx.x * blockDim.x + threadIdx.x;   // B_*64*HID_ = 131072
    int ch = gid & (HID_ - 1);
    int c  = (gid >> 10) & 63;
    int b  = gid >> 16;
    int d  = ch & 63;
    int pd = ch ^ 32;
    float sign = (d < 32) ? -1.f : 1.f;
    float g = g_gfac;

    float u = 0.f;
    #pragma unroll 2
    for (int p = 63; p >= 0; p--) {
        int s = c * 64 + p;
        size_t row = (size_t)b * S_ + s;
        float kvp = kv_recompute(row, s, ch, pd, d, sign, cosb, sinb);
        u = fmaf(g, u, kvp);
    }
    g_T[gid] = u;
}

// 5b) chunk-carry suffix combine (per channel)
__global__ void scanB_kernel() {
    int t = blockIdx.x * blockDim.x + threadIdx.x;     // B_*HID_ = 2048
    if (t >= B_ * HID_) return;
    int ch = t & (HID_ - 1);
    int b  = t >> 10;
    float gL = expf(g_apos * 64.f);
    float usuf = 0.f;
    for (int c = 63; c >= 0; c--) {
        int i = (b * 64 + c) * HID_ + ch;
        g_carry[i] = usuf;
        usuf = fmaf(gL, usuf, g_T[i]);
    }
}

// 5c) pass 2: recompute local scan + finalize + gate; write high-term only
__global__ void scanC_kernel(const float* __restrict__ cosb,
                             const float* __restrict__ sinb,
                             const float* __restrict__ tf) {
    int gid = blockIdx.x * blockDim.x + threadIdx.x;   // B_*64*HID_
    int ch = gid & (HID_ - 1);
    int c  = (gid >> 10) & 63;
    int b  = gid >> 16;
    int d  = ch & 63;
    int pd = ch ^ 32;
    float sign = (d < 32) ? -1.f : 1.f;
    float a = g_apos;
    float g = g_gfac;
    float tfv = tf[ch];
    float carry = g_carry[(b * 64 + c) * HID_ + ch];
    float inv_em1 = 1.f / expm1f(a);

    float u = 0.f;
    #pragma unroll 2
    for (int p = 63; p >= 0; p--) {
        int s = c * 64 + p;
        size_t row = (size_t)b * S_ + s;
        float rr, kvp;
        rkv_recompute(row, s, ch, pd, d, sign, cosb, sinb, rr, kvp);
        u = fmaf(g, u, kvp);   // == uloc[p]
        float U = u + expf(a * (float)(64 - p)) * carry;
        float den = expm1f(a * (float)(S_ - s)) * inv_em1;
        float wkv = U / (den + 1e-8f);
        float att = rr * (tfv * kvp + wkv);
        g_A2[row * KSP + ch] = __float2half_rn(att);   // high term only
    }
}

// ---------------------------------------------------------------------------
// launch
// ---------------------------------------------------------------------------
extern "C" void kernel_launch(void* const* d_in, const int* in_sizes, int n_in,
                              void* d_out, int out_size) {
    const float* hidden = (const float*)d_in[0];
    const float* cosb   = (const float*)d_in[1];
    const float* sinb   = (const float*)d_in[2];
    const float* W_rkv  = (const float*)d_in[3];
    const float* W_o    = (const float*)d_in[4];
    const float* tdec   = (const float*)d_in[5];
    const float* tfirst = (const float*)d_in[6];
    const float* tmix   = (const float*)d_in[7];
    float* out = (float*)d_out;

    __half *A2, *B2rkv, *B2o;
    float *rkv;
    cudaGetSymbolAddress((void**)&A2,    g_A2);
    cudaGetSymbolAddress((void**)&B2rkv, g_B2rkv);
    cudaGetSymbolAddress((void**)&B2o,   g_B2o);
    cudaGetSymbolAddress((void**)&rkv,   g_rkv);

    cudaFuncSetAttribute(gemm_hmma,
                         cudaFuncAttributeMaxDynamicSharedMemorySize, SMEM_DYN);

    // (1) scalar decay factor
    prep_kernel<<<1, 256>>>(tdec);
    // (2) token mix + split
    mix_split_kernel<<<(M_ * HID_ / 4 + 255) / 256, 256>>>(hidden, tmix);
    // (3) W_rkv split
    wsplit_kernel<<<(N1_ * HID_ / 4 + 255) / 256, 256>>>(W_rkv, B2rkv, N1_);
    // (4) GEMM1 merged: kv cols (K=2048) + r cols (K=1024) in one launch
    gemm_hmma<<<dim3(24, M_ / BM_T), 128, SMEM_DYN>>>(
        A2, B2rkv, rkv, N1_, 0, 0);
    // (5) W_o split
    wsplit_kernel<<<(N2_ * HID_ / 4 + 255) / 256, 256>>>(W_o, B2o, N2_);
    // (6) pass 1: chunk totals (k/v only)
    scanA_kernel<<<(B_ * 64 * HID_) / 256, 256>>>(cosb, sinb);
    // (7) chunk-carry combine
    scanB_kernel<<<(B_ * HID_ + 255) / 256, 256>>>();
    // (8) pass 2: recompute + finalize + gate (high-term write)
    scanC_kernel<<<(B_ * 64 * HID_) / 256, 256>>>(cosb, sinb, tfirst);
    // (9) GEMM2: out = att_h @ W_o^T (single-term, K=1024)
    gemm_hmma<<<dim3(N2_ / BN_T, M_ / BM_T), 128, SMEM_DYN>>>(
        A2, B2o, out, N2_, 1024, 0);
}

// round 16
// speedup vs baseline: 2.4205x; 1.2573x over previous
#include <cuda_runtime.h>
#include <cuda_fp16.h>
#include <stdint.h>
#include <math.h>

// Problem constants
#define B_   2
#define S_   4096
#define HID_ 1024
#define H_   16
#define D_   64
#define M_   (B_*S_)        // 8192
#define N1_  (3*H_*D_)      // 3072
#define N2_  HID_           // 1024
#define KH   1024           // plain fp16 GEMM K

// ---------------------------------------------------------------------------
// Scratch (no cudaMalloc allowed)
// ---------------------------------------------------------------------------
__device__ __align__(256) __half g_A2[(size_t)M_*KH];         // 16.8 MB
__device__ __align__(256) __half g_B2rkv[(size_t)N1_*KH];     //  6.3 MB
__device__ __align__(256) __half g_B2o[(size_t)N2_*KH];       //  2.1 MB
__device__ __align__(256) float g_rkv[(size_t)M_*N1_];        // 100.7 MB
__device__ __align__(256) float g_T[(size_t)B_*64*HID_];      //   0.5 MB
__device__ __align__(256) float g_carry[(size_t)B_*64*HID_];  //   0.5 MB
__device__ float g_gfac;   // exp(a)
__device__ float g_apos;   // a = mean(exp(time_decay)) = -avg_decay

// ---------------------------------------------------------------------------
// helpers
// ---------------------------------------------------------------------------
__device__ __forceinline__ uint32_t smem_u32(const void* p) {
    uint32_t a;
    asm("{ .reg .u64 t; cvta.to.shared.u64 t, %1; cvt.u32.u64 %0, t; }" : "=r"(a) : "l"(p));
    return a;
}
__device__ __forceinline__ void cp16(uint32_t dst, const void* src) {
    asm volatile("cp.async.cg.shared.global [%0], [%1], 16;" :: "r"(dst), "l"(src));
}
__device__ __forceinline__ void ldm_x4(uint32_t* r, uint32_t addr) {
    asm volatile("ldmatrix.sync.aligned.m8n8.x4.shared.b16 {%0,%1,%2,%3}, [%4];"
                 : "=r"(r[0]), "=r"(r[1]), "=r"(r[2]), "=r"(r[3]) : "r"(addr));
}
__device__ __forceinline__ void mma16816(float* c, const uint32_t* a, const uint32_t* b) {
    asm volatile(
        "mma.sync.aligned.m16n8k16.row.col.f32.f16.f16.f32 "
        "{%0,%1,%2,%3}, {%4,%5,%6,%7}, {%8,%9}, {%0,%1,%2,%3};"
        : "+f"(c[0]), "+f"(c[1]), "+f"(c[2]), "+f"(c[3])
        : "r"(a[0]), "r"(a[1]), "r"(a[2]), "r"(a[3]), "r"(b[0]), "r"(b[1]));
}

// ---------------------------------------------------------------------------
// fp16 HMMA GEMM: C[:, x*128..] = A[M,1024] * B[N,1024]^T, fp32 out.
// CTA tile 128x128, BK=64 (NKT=16), 3-stage cp.async ring, one sync/K-tile.
// 4 warps, 64x64/warp, frag double-buffering. 2 CTAs/SM.
// ---------------------------------------------------------------------------
#define BK 64
#define NKT (KH/BK)            // 16
#define NSTG 3
#define LDS_ (BK + 8)          // 72
#define BM_T 128
#define BN_T 128
#define A_E (BM_T*LDS_)        // 9216 elems
#define B_E (BN_T*LDS_)        // 9216 elems
#define STG_B ((A_E+B_E)*2)    // 36864 B per stage
#define SMEM_DYN (NSTG*STG_B)  // 110592 B

__global__ void __launch_bounds__(128, 2)
gemm_hmma(const __half* __restrict__ A,
          const __half* __restrict__ Bm,
          float* __restrict__ C, int N) {
    extern __shared__ __half smem[];
    const uint32_t sb = smem_u32(smem);

    const int tid = threadIdx.x;
    const int wid = tid >> 5, lane = tid & 31;
    const int bm = blockIdx.y * BM_T;
    const int bn = blockIdx.x * BN_T;
    const int wm = (wid & 1) * 64;
    const int wn = (wid >> 1) * 64;

    float acc[4][8][4];
    #pragma unroll
    for (int i = 0; i < 4; i++)
        #pragma unroll
        for (int j = 0; j < 8; j++)
            #pragma unroll
            for (int q = 0; q < 4; q++) acc[i][j][q] = 0.f;

    const int a_r = lane & 15, a_k = (lane >> 4) << 3;
    const int b_r = (lane & 7) + ((lane >> 4) << 3), b_k = ((lane >> 3) & 1) << 3;
    const uint32_t aoff = (uint32_t)((wm + a_r) * LDS_ + a_k) * 2;
    const uint32_t boff = (uint32_t)((wn + b_r) * LDS_ + b_k) * 2 + A_E * 2;

    auto load_tile = [&](int kt, int st) {
        const size_t k0 = (size_t)kt * BK;
        uint32_t da = sb + (uint32_t)st * STG_B;
        uint32_t db = da + A_E * 2;
        #pragma unroll
        for (int j = 0; j < 8; j++) {
            int c = tid + j * 128;
            int r = c >> 3, k = (c & 7) * 8;
            cp16(da + (uint32_t)(r * LDS_ + k) * 2,
                 A + (size_t)(bm + r) * KH + k0 + k);
        }
        #pragma unroll
        for (int j = 0; j < 8; j++) {
            int c = tid + j * 128;
            int r = c >> 3, k = (c & 7) * 8;
            cp16(db + (uint32_t)(r * LDS_ + k) * 2,
                 Bm + (size_t)(bn + r) * KH + k0 + k);
        }
        asm volatile("cp.async.commit_group;" ::: "memory");
    };

    load_tile(0, 0);
    load_tile(1, 1);

    uint32_t af[2][4][4];
    uint32_t bf[2][8][2];

    for (int kt = 0; kt < NKT; kt++) {
        const int st = kt % NSTG;
        if (kt < NKT - 1) asm volatile("cp.async.wait_group 1;" ::: "memory");
        else              asm volatile("cp.async.wait_group 0;" ::: "memory");
        __syncthreads();

        const int nt = kt + NSTG - 1;
        if (nt < NKT) load_tile(nt, nt % NSTG);

        const uint32_t stg = sb + (uint32_t)st * STG_B;

        #pragma unroll
        for (int mi = 0; mi < 4; mi++)
            ldm_x4(af[0][mi], stg + aoff + (uint32_t)(mi * 16 * LDS_) * 2);
        #pragma unroll
        for (int p = 0; p < 4; p++) {
            uint32_t r[4];
            ldm_x4(r, stg + boff + (uint32_t)(p * 16 * LDS_) * 2);
            bf[0][p * 2 + 0][0] = r[0]; bf[0][p * 2 + 0][1] = r[1];
            bf[0][p * 2 + 1][0] = r[2]; bf[0][p * 2 + 1][1] = r[3];
        }

        #pragma unroll
        for (int ks = 0; ks < BK / 16; ks++) {
            const int cur = ks & 1, nxt = cur ^ 1;
            if (ks < BK / 16 - 1) {
                const uint32_t kb = (uint32_t)((ks + 1) * 16 * 2);
                #pragma unroll
                for (int mi = 0; mi < 4; mi++)
                    ldm_x4(af[nxt][mi], stg + aoff + (uint32_t)(mi * 16 * LDS_) * 2 + kb);
                #pragma unroll
                for (int p = 0; p < 4; p++) {
                    uint32_t r[4];
                    ldm_x4(r, stg + boff + (uint32_t)(p * 16 * LDS_) * 2 + kb);
                    bf[nxt][p * 2 + 0][0] = r[0]; bf[nxt][p * 2 + 0][1] = r[1];
                    bf[nxt][p * 2 + 1][0] = r[2]; bf[nxt][p * 2 + 1][1] = r[3];
                }
            }
            #pragma unroll
            for (int mi = 0; mi < 4; mi++)
                #pragma unroll
                for (int nj = 0; nj < 8; nj++)
                    mma16816(acc[mi][nj], af[cur][mi], bf[cur][nj]);
        }
    }

    // epilogue
    const int er = lane >> 2, ec = (lane & 3) * 2;
    #pragma unroll
    for (int mi = 0; mi < 4; mi++) {
        #pragma unroll
        for (int nj = 0; nj < 8; nj++) {
            size_t row0 = (size_t)(bm + wm + mi * 16 + er);
            size_t col  = (size_t)(bn + wn + nj * 8 + ec);
            float2 v0 = make_float2(acc[mi][nj][0], acc[mi][nj][1]);
            float2 v1 = make_float2(acc[mi][nj][2], acc[mi][nj][3]);
            *(float2*)(C + row0 * N + col)       = v0;
            *(float2*)(C + (row0 + 8) * N + col) = v1;
        }
    }
}

// 1) token mix -> fp16 A2
__global__ void mix_split_kernel(const float* __restrict__ hsrc,
                                 const float* __restrict__ tm) {
    int i4 = blockIdx.x * blockDim.x + threadIdx.x;
    if (i4 >= M_ * HID_ / 4) return;
    int e = i4 * 4;
    int col = e & (HID_ - 1);
    int row = e >> 10;
    int s = row & (S_ - 1);
    float4 hv = *(const float4*)(hsrc + e);
    float4 tv = *(const float4*)(tm + col);
    float4 pv = make_float4(0.f, 0.f, 0.f, 0.f);
    if (s) pv = *(const float4*)(hsrc + e - HID_);
    __half h[4];
    h[0] = __float2half_rn(hv.x * tv.x + pv.x * (1.f - tv.x));
    h[1] = __float2half_rn(hv.y * tv.y + pv.y * (1.f - tv.y));
    h[2] = __float2half_rn(hv.z * tv.z + pv.z * (1.f - tv.z));
    h[3] = __float2half_rn(hv.w * tv.w + pv.w * (1.f - tv.w));
    *(uint64_t*)(g_A2 + (size_t)row * KH + col) = *(uint64_t*)h;
}

// weight -> fp16
__global__ void wsplit_kernel(const float* __restrict__ W,
                              __half* __restrict__ out, int rows) {
    int i4 = blockIdx.x * blockDim.x + threadIdx.x;
    if (i4 >= rows * (HID_ / 4)) return;
    int e = i4 * 4;
    float4 w = *(const float4*)(W + e);
    __half h[4] = { __float2half_rn(w.x), __float2half_rn(w.y),
                    __float2half_rn(w.z), __float2half_rn(w.w) };
    *(uint64_t*)(out + e) = *(uint64_t*)h;
}

// 4) scalar decay factor: a = mean(exp(td)), g = exp(a)
__global__ void prep_kernel(const float* __restrict__ td) {
    __shared__ float red[256];
    float s = 0.f;
    for (int i = threadIdx.x; i < H_ * D_; i += 256) s += expf(td[i]);
    red[threadIdx.x] = s;
    __syncthreads();
    for (int w = 128; w > 0; w >>= 1) {
        if (threadIdx.x < w) red[threadIdx.x] += red[threadIdx.x + w];
        __syncthreads();
    }
    if (threadIdx.x == 0) {
        float a = red[0] / (float)(H_ * D_);
        g_apos = a;
        g_gfac = expf(a);
    }
}

// kv-only recompute
__device__ __forceinline__ float kv_recompute(
    size_t row, int s, int ch, int pd, int d, float sign,
    const float* __restrict__ cosb, const float* __restrict__ sinb)
{
    const float* base = g_rkv + row * N1_;
    float kvv = base[1024 + ch];
    float kpv = base[1024 + pd];
    float vv  = base[2048 + ch];
    float cc = cosb[s * 64 + d];
    float sn = sinb[s * 64 + d];
    float kk = kvv * cc + sign * kpv * sn;
    return kk * vv;
}

// full recompute
__device__ __forceinline__ void rkv_recompute(
    size_t row, int s, int ch, int pd, int d, float sign,
    const float* __restrict__ cosb, const float* __restrict__ sinb,
    float& rr, float& kvp)
{
    const float* base = g_rkv + row * N1_;
    float rv  = base[ch];
    float rpv = base[pd];
    float kvv = base[1024 + ch];
    float kpv = base[1024 + pd];
    float vv  = base[2048 + ch];
    float cc = cosb[s * 64 + d];
    float sn = sinb[s * 64 + d];
    float rs  = 1.f / (1.f + __expf(-rv));
    float rps = 1.f / (1.f + __expf(-rpv));
    rr  = rs * cc + sign * rps * sn;
    float kk = kvv * cc + sign * kpv * sn;
    kvp = kk * vv;
}

// 5a) pass 1: per-chunk decayed suffix totals only (k/v reads only)
__global__ void scanA_kernel(const float* __restrict__ cosb,
                             const float* __restrict__ sinb) {
    int gid = blockIdx.x * blockDim.x + threadIdx.x;   // B_*64*HID_ = 131072
    int ch = gid & (HID_ - 1);
    int c  = (gid >> 10) & 63;
    int b  = gid >> 16;
    int d  = ch & 63;
    int pd = ch ^ 32;
    float sign = (d < 32) ? -1.f : 1.f;
    float g = g_gfac;

    float u = 0.f;
    #pragma unroll 2
    for (int p = 63; p >= 0; p--) {
        int s = c * 64 + p;
        size_t row = (size_t)b * S_ + s;
        float kvp = kv_recompute(row, s, ch, pd, d, sign, cosb, sinb);
        u = fmaf(g, u, kvp);
    }
    g_T[gid] = u;
}

// 5b) chunk-carry suffix combine (per channel)
__global__ void scanB_kernel() {
    int t = blockIdx.x * blockDim.x + threadIdx.x;     // B_*HID_ = 2048
    if (t >= B_ * HID_) return;
    int ch = t & (HID_ - 1);
    int b  = t >> 10;
    float gL = expf(g_apos * 64.f);
    float usuf = 0.f;
    for (int c = 63; c >= 0; c--) {
        int i = (b * 64 + c) * HID_ + ch;
        g_carry[i] = usuf;
        usuf = fmaf(gL, usuf, g_T[i]);
    }
}

// 5c) pass 2: recompute local scan + finalize + gate -> fp16 A2
__global__ void scanC_kernel(const float* __restrict__ cosb,
                             const float* __restrict__ sinb,
                             const float* __restrict__ tf) {
    int gid = blockIdx.x * blockDim.x + threadIdx.x;   // B_*64*HID_
    int ch = gid & (HID_ - 1);
    int c  = (gid >> 10) & 63;
    int b  = gid >> 16;
    int d  = ch & 63;
    int pd = ch ^ 32;
    float sign = (d < 32) ? -1.f : 1.f;
    float a = g_apos;
    float g = g_gfac;
    float tfv = tf[ch];
    float carry = g_carry[(b * 64 + c) * HID_ + ch];
    float inv_em1 = 1.f / expm1f(a);

    float u = 0.f;
    #pragma unroll 2
    for (int p = 63; p >= 0; p--) {
        int s = c * 64 + p;
        size_t row = (size_t)b * S_ + s;
        float rr, kvp;
        rkv_recompute(row, s, ch, pd, d, sign, cosb, sinb, rr, kvp);
        u = fmaf(g, u, kvp);   // == uloc[p]
        float U = u + expf(a * (float)(64 - p)) * carry;
        float den = expm1f(a * (float)(S_ - s)) * inv_em1;
        float wkv = U / (den + 1e-8f);
        float att = rr * (tfv * kvp + wkv);
        g_A2[row * KH + ch] = __float2half_rn(att);
    }
}

// ---------------------------------------------------------------------------
// launch
// ---------------------------------------------------------------------------
extern "C" void kernel_launch(void* const* d_in, const int* in_sizes, int n_in,
                              void* d_out, int out_size) {
    const float* hidden = (const float*)d_in[0];
    const float* cosb   = (const float*)d_in[1];
    const float* sinb   = (const float*)d_in[2];
    const float* W_rkv  = (const float*)d_in[3];
    const float* W_o    = (const float*)d_in[4];
    const float* tdec   = (const float*)d_in[5];
    const float* tfirst = (const float*)d_in[6];
    const float* tmix   = (const float*)d_in[7];
    float* out = (float*)d_out;

    __half *A2, *B2rkv, *B2o;
    float *rkv;
    cudaGetSymbolAddress((void**)&A2,    g_A2);
    cudaGetSymbolAddress((void**)&B2rkv, g_B2rkv);
    cudaGetSymbolAddress((void**)&B2o,   g_B2o);
    cudaGetSymbolAddress((void**)&rkv,   g_rkv);

    cudaFuncSetAttribute(gemm_hmma,
                         cudaFuncAttributeMaxDynamicSharedMemorySize, SMEM_DYN);

    // (1) scalar decay factor
    prep_kernel<<<1, 256>>>(tdec);
    // (2) token mix -> fp16
    mix_split_kernel<<<(M_ * HID_ / 4 + 255) / 256, 256>>>(hidden, tmix);
    // (3) W_rkv -> fp16
    wsplit_kernel<<<(N1_ * HID_ / 4 + 255) / 256, 256>>>(W_rkv, B2rkv, N1_);
    // (4) GEMM1: rkv = mixed @ W_rkv^T
    gemm_hmma<<<dim3(N1_ / BN_T, M_ / BM_T), 128, SMEM_DYN>>>(A2, B2rkv, rkv, N1_);
    // (5) W_o -> fp16
    wsplit_kernel<<<(N2_ * HID_ / 4 + 255) / 256, 256>>>(W_o, B2o, N2_);
    // (6) pass 1: chunk totals (k/v only)
    scanA_kernel<<<(B_ * 64 * HID_) / 256, 256>>>(cosb, sinb);
    // (7) chunk-carry combine
    scanB_kernel<<<(B_ * HID_ + 255) / 256, 256>>>();
    // (8) pass 2: recompute + finalize + gate -> fp16
    scanC_kernel<<<(B_ * 64 * HID_) / 256, 256>>>(cosb, sinb, tfirst);
    // (9) GEMM2: out = att @ W_o^T
    gemm_hmma<<<dim3(N2_ / BN_T, M_ / BM_T), 128, SMEM_DYN>>>(A2, B2o, out, N2_);
}

// round 17
// speedup vs baseline: 2.4835x; 1.0260x over previous
#include <cuda_runtime.h>
#include <cuda_fp16.h>
#include <stdint.h>
#include <math.h>

// Problem constants
#define B_   2
#define S_   4096
#define HID_ 1024
#define H_   16
#define D_   64
#define M_   (B_*S_)        // 8192
#define N1_  (3*H_*D_)      // 3072
#define N2_  HID_           // 1024
#define KH   1024           // plain fp16 GEMM K

// ---------------------------------------------------------------------------
// Scratch (no cudaMalloc allowed)
// ---------------------------------------------------------------------------
__device__ __align__(256) __half g_A2[(size_t)M_*KH];         // 16.8 MB
__device__ __align__(256) __half g_B2rkv[(size_t)N1_*KH];     //  6.3 MB
__device__ __align__(256) __half g_B2o[(size_t)N2_*KH];       //  2.1 MB
__device__ __align__(256) __half g_rkv[(size_t)M_*N1_];       // 50.3 MB (fp16 now)
__device__ __align__(256) float g_T[(size_t)B_*64*HID_];      //   0.5 MB
__device__ __align__(256) float g_carry[(size_t)B_*64*HID_];  //   0.5 MB
__device__ float g_gfac;   // exp(a)
__device__ float g_apos;   // a = mean(exp(time_decay)) = -avg_decay

// ---------------------------------------------------------------------------
// helpers
// ---------------------------------------------------------------------------
__device__ __forceinline__ uint32_t smem_u32(const void* p) {
    uint32_t a;
    asm("{ .reg .u64 t; cvta.to.shared.u64 t, %1; cvt.u32.u64 %0, t; }" : "=r"(a) : "l"(p));
    return a;
}
__device__ __forceinline__ void cp16(uint32_t dst, const void* src) {
    asm volatile("cp.async.cg.shared.global [%0], [%1], 16;" :: "r"(dst), "l"(src));
}
__device__ __forceinline__ void ldm_x4(uint32_t* r, uint32_t addr) {
    asm volatile("ldmatrix.sync.aligned.m8n8.x4.shared.b16 {%0,%1,%2,%3}, [%4];"
                 : "=r"(r[0]), "=r"(r[1]), "=r"(r[2]), "=r"(r[3]) : "r"(addr));
}
__device__ __forceinline__ void mma16816(float* c, const uint32_t* a, const uint32_t* b) {
    asm volatile(
        "mma.sync.aligned.m16n8k16.row.col.f32.f16.f16.f32 "
        "{%0,%1,%2,%3}, {%4,%5,%6,%7}, {%8,%9}, {%0,%1,%2,%3};"
        : "+f"(c[0]), "+f"(c[1]), "+f"(c[2]), "+f"(c[3])
        : "r"(a[0]), "r"(a[1]), "r"(a[2]), "r"(a[3]), "r"(b[0]), "r"(b[1]));
}

// ---------------------------------------------------------------------------
// fp16 HMMA GEMM: C[:, x*128..] = A[M,1024] * B[N,1024]^T.
// OutT = __half (GEMM1, fp16 intermediate) or float (GEMM2, final output).
// CTA tile 128x128, BK=64 (NKT=16), 3-stage cp.async ring, one sync/K-tile.
// 4 warps, 64x64/warp, frag double-buffering. 2 CTAs/SM.
// ---------------------------------------------------------------------------
#define BK 64
#define NKT (KH/BK)            // 16
#define NSTG 3
#define LDS_ (BK + 8)          // 72
#define BM_T 128
#define BN_T 128
#define A_E (BM_T*LDS_)        // 9216 elems
#define B_E (BN_T*LDS_)        // 9216 elems
#define STG_B ((A_E+B_E)*2)    // 36864 B per stage
#define SMEM_DYN (NSTG*STG_B)  // 110592 B

template <typename OutT>
__global__ void __launch_bounds__(128, 2)
gemm_hmma(const __half* __restrict__ A,
          const __half* __restrict__ Bm,
          OutT* __restrict__ C, int N) {
    extern __shared__ __half smem[];
    const uint32_t sb = smem_u32(smem);

    const int tid = threadIdx.x;
    const int wid = tid >> 5, lane = tid & 31;
    const int bm = blockIdx.y * BM_T;
    const int bn = blockIdx.x * BN_T;
    const int wm = (wid & 1) * 64;
    const int wn = (wid >> 1) * 64;

    float acc[4][8][4];
    #pragma unroll
    for (int i = 0; i < 4; i++)
        #pragma unroll
        for (int j = 0; j < 8; j++)
            #pragma unroll
            for (int q = 0; q < 4; q++) acc[i][j][q] = 0.f;

    const int a_r = lane & 15, a_k = (lane >> 4) << 3;
    const int b_r = (lane & 7) + ((lane >> 4) << 3), b_k = ((lane >> 3) & 1) << 3;
    const uint32_t aoff = (uint32_t)((wm + a_r) * LDS_ + a_k) * 2;
    const uint32_t boff = (uint32_t)((wn + b_r) * LDS_ + b_k) * 2 + A_E * 2;

    auto load_tile = [&](int kt, int st) {
        const size_t k0 = (size_t)kt * BK;
        uint32_t da = sb + (uint32_t)st * STG_B;
        uint32_t db = da + A_E * 2;
        #pragma unroll
        for (int j = 0; j < 8; j++) {
            int c = tid + j * 128;
            int r = c >> 3, k = (c & 7) * 8;
            cp16(da + (uint32_t)(r * LDS_ + k) * 2,
                 A + (size_t)(bm + r) * KH + k0 + k);
        }
        #pragma unroll
        for (int j = 0; j < 8; j++) {
            int c = tid + j * 128;
            int r = c >> 3, k = (c & 7) * 8;
            cp16(db + (uint32_t)(r * LDS_ + k) * 2,
                 Bm + (size_t)(bn + r) * KH + k0 + k);
        }
        asm volatile("cp.async.commit_group;" ::: "memory");
    };

    load_tile(0, 0);
    load_tile(1, 1);

    uint32_t af[2][4][4];
    uint32_t bf[2][8][2];

    for (int kt = 0; kt < NKT; kt++) {
        const int st = kt % NSTG;
        if (kt < NKT - 1) asm volatile("cp.async.wait_group 1;" ::: "memory");
        else              asm volatile("cp.async.wait_group 0;" ::: "memory");
        __syncthreads();

        const int nt = kt + NSTG - 1;
        if (nt < NKT) load_tile(nt, nt % NSTG);

        const uint32_t stg = sb + (uint32_t)st * STG_B;

        #pragma unroll
        for (int mi = 0; mi < 4; mi++)
            ldm_x4(af[0][mi], stg + aoff + (uint32_t)(mi * 16 * LDS_) * 2);
        #pragma unroll
        for (int p = 0; p < 4; p++) {
            uint32_t r[4];
            ldm_x4(r, stg + boff + (uint32_t)(p * 16 * LDS_) * 2);
            bf[0][p * 2 + 0][0] = r[0]; bf[0][p * 2 + 0][1] = r[1];
            bf[0][p * 2 + 1][0] = r[2]; bf[0][p * 2 + 1][1] = r[3];
        }

        #pragma unroll
        for (int ks = 0; ks < BK / 16; ks++) {
            const int cur = ks & 1, nxt = cur ^ 1;
            if (ks < BK / 16 - 1) {
                const uint32_t kb = (uint32_t)((ks + 1) * 16 * 2);
                #pragma unroll
                for (int mi = 0; mi < 4; mi++)
                    ldm_x4(af[nxt][mi], stg + aoff + (uint32_t)(mi * 16 * LDS_) * 2 + kb);
                #pragma unroll
                for (int p = 0; p < 4; p++) {
                    uint32_t r[4];
                    ldm_x4(r, stg + boff + (uint32_t)(p * 16 * LDS_) * 2 + kb);
                    bf[nxt][p * 2 + 0][0] = r[0]; bf[nxt][p * 2 + 0][1] = r[1];
                    bf[nxt][p * 2 + 1][0] = r[2]; bf[nxt][p * 2 + 1][1] = r[3];
                }
            }
            #pragma unroll
            for (int mi = 0; mi < 4; mi++)
                #pragma unroll
                for (int nj = 0; nj < 8; nj++)
                    mma16816(acc[mi][nj], af[cur][mi], bf[cur][nj]);
        }
    }

    // epilogue
    const int er = lane >> 2, ec = (lane & 3) * 2;
    #pragma unroll
    for (int mi = 0; mi < 4; mi++) {
        #pragma unroll
        for (int nj = 0; nj < 8; nj++) {
            size_t row0 = (size_t)(bm + wm + mi * 16 + er);
            size_t col  = (size_t)(bn + wn + nj * 8 + ec);
            if constexpr (sizeof(OutT) == 2) {
                *(__half2*)(C + row0 * N + col) =
                    __floats2half2_rn(acc[mi][nj][0], acc[mi][nj][1]);
                *(__half2*)(C + (row0 + 8) * N + col) =
                    __floats2half2_rn(acc[mi][nj][2], acc[mi][nj][3]);
            } else {
                *(float2*)(C + row0 * N + col) =
                    make_float2(acc[mi][nj][0], acc[mi][nj][1]);
                *(float2*)(C + (row0 + 8) * N + col) =
                    make_float2(acc[mi][nj][2], acc[mi][nj][3]);
            }
        }
    }
}

// 1) token mix -> fp16 A2
__global__ void mix_split_kernel(const float* __restrict__ hsrc,
                                 const float* __restrict__ tm) {
    int i4 = blockIdx.x * blockDim.x + threadIdx.x;
    if (i4 >= M_ * HID_ / 4) return;
    int e = i4 * 4;
    int col = e & (HID_ - 1);
    int row = e >> 10;
    int s = row & (S_ - 1);
    float4 hv = *(const float4*)(hsrc + e);
    float4 tv = *(const float4*)(tm + col);
    float4 pv = make_float4(0.f, 0.f, 0.f, 0.f);
    if (s) pv = *(const float4*)(hsrc + e - HID_);
    __half h[4];
    h[0] = __float2half_rn(hv.x * tv.x + pv.x * (1.f - tv.x));
    h[1] = __float2half_rn(hv.y * tv.y + pv.y * (1.f - tv.y));
    h[2] = __float2half_rn(hv.z * tv.z + pv.z * (1.f - tv.z));
    h[3] = __float2half_rn(hv.w * tv.w + pv.w * (1.f - tv.w));
    *(uint64_t*)(g_A2 + (size_t)row * KH + col) = *(uint64_t*)h;
}

// weight -> fp16
__global__ void wsplit_kernel(const float* __restrict__ W,
                              __half* __restrict__ out, int rows) {
    int i4 = blockIdx.x * blockDim.x + threadIdx.x;
    if (i4 >= rows * (HID_ / 4)) return;
    int e = i4 * 4;
    float4 w = *(const float4*)(W + e);
    __half h[4] = { __float2half_rn(w.x), __float2half_rn(w.y),
                    __float2half_rn(w.z), __float2half_rn(w.w) };
    *(uint64_t*)(out + e) = *(uint64_t*)h;
}

// 4) scalar decay factor: a = mean(exp(td)), g = exp(a)
__global__ void prep_kernel(const float* __restrict__ td) {
    __shared__ float red[256];
    float s = 0.f;
    for (int i = threadIdx.x; i < H_ * D_; i += 256) s += expf(td[i]);
    red[threadIdx.x] = s;
    __syncthreads();
    for (int w = 128; w > 0; w >>= 1) {
        if (threadIdx.x < w) red[threadIdx.x] += red[threadIdx.x + w];
        __syncthreads();
    }
    if (threadIdx.x == 0) {
        float a = red[0] / (float)(H_ * D_);
        g_apos = a;
        g_gfac = expf(a);
    }
}

// kv-only recompute (fp16 rkv reads)
__device__ __forceinline__ float kv_recompute(
    size_t row, int s, int ch, int pd, int d, float sign,
    const float* __restrict__ cosb, const float* __restrict__ sinb)
{
    const __half* base = g_rkv + row * N1_;
    float kvv = __half2float(base[1024 + ch]);
    float kpv = __half2float(base[1024 + pd]);
    float vv  = __half2float(base[2048 + ch]);
    float cc = cosb[s * 64 + d];
    float sn = sinb[s * 64 + d];
    float kk = kvv * cc + sign * kpv * sn;
    return kk * vv;
}

// full recompute (fp16 rkv reads)
__device__ __forceinline__ void rkv_recompute(
    size_t row, int s, int ch, int pd, int d, float sign,
    const float* __restrict__ cosb, const float* __restrict__ sinb,
    float& rr, float& kvp)
{
    const __half* base = g_rkv + row * N1_;
    float rv  = __half2float(base[ch]);
    float rpv = __half2float(base[pd]);
    float kvv = __half2float(base[1024 + ch]);
    float kpv = __half2float(base[1024 + pd]);
    float vv  = __half2float(base[2048 + ch]);
    float cc = cosb[s * 64 + d];
    float sn = sinb[s * 64 + d];
    float rs  = 1.f / (1.f + __expf(-rv));
    float rps = 1.f / (1.f + __expf(-rpv));
    rr  = rs * cc + sign * rps * sn;
    float kk = kvv * cc + sign * kpv * sn;
    kvp = kk * vv;
}

// 5a) pass 1: per-chunk decayed suffix totals only
__global__ void scanA_kernel(const float* __restrict__ cosb,
                             const float* __restrict__ sinb) {
    int gid = blockIdx.x * blockDim.x + threadIdx.x;   // B_*64*HID_ = 131072
    int ch = gid & (HID_ - 1);
    int c  = (gid >> 10) & 63;
    int b  = gid >> 16;
    int d  = ch & 63;
    int pd = ch ^ 32;
    float sign = (d < 32) ? -1.f : 1.f;
    float g = g_gfac;

    float u = 0.f;
    #pragma unroll 2
    for (int p = 63; p >= 0; p--) {
        int s = c * 64 + p;
        size_t row = (size_t)b * S_ + s;
        float kvp = kv_recompute(row, s, ch, pd, d, sign, cosb, sinb);
        u = fmaf(g, u, kvp);
    }
    g_T[gid] = u;
}

// 5b) chunk-carry suffix combine (per channel)
__global__ void scanB_kernel() {
    int t = blockIdx.x * blockDim.x + threadIdx.x;     // B_*HID_ = 2048
    if (t >= B_ * HID_) return;
    int ch = t & (HID_ - 1);
    int b  = t >> 10;
    float gL = expf(g_apos * 64.f);
    float usuf = 0.f;
    for (int c = 63; c >= 0; c--) {
        int i = (b * 64 + c) * HID_ + ch;
        g_carry[i] = usuf;
        usuf = fmaf(gL, usuf, g_T[i]);
    }
}

// 5c) pass 2: recompute local scan + finalize + gate -> fp16 A2
__global__ void scanC_kernel(const float* __restrict__ cosb,
                             const float* __restrict__ sinb,
                             const float* __restrict__ tf) {
    int gid = blockIdx.x * blockDim.x + threadIdx.x;   // B_*64*HID_
    int ch = gid & (HID_ - 1);
    int c  = (gid >> 10) & 63;
    int b  = gid >> 16;
    int d  = ch & 63;
    int pd = ch ^ 32;
    float sign = (d < 32) ? -1.f : 1.f;
    float a = g_apos;
    float g = g_gfac;
    float tfv = tf[ch];
    float carry = g_carry[(b * 64 + c) * HID_ + ch];
    float inv_em1 = 1.f / expm1f(a);

    float u = 0.f;
    #pragma unroll 2
    for (int p = 63; p >= 0; p--) {
        int s = c * 64 + p;
        size_t row = (size_t)b * S_ + s;
        float rr, kvp;
        rkv_recompute(row, s, ch, pd, d, sign, cosb, sinb, rr, kvp);
        u = fmaf(g, u, kvp);   // == uloc[p]
        float U = u + expf(a * (float)(64 - p)) * carry;
        float den = expm1f(a * (float)(S_ - s)) * inv_em1;
        float wkv = U / (den + 1e-8f);
        float att = rr * (tfv * kvp + wkv);
        g_A2[row * KH + ch] = __float2half_rn(att);
    }
}

// ---------------------------------------------------------------------------
// launch
// ---------------------------------------------------------------------------
extern "C" void kernel_launch(void* const* d_in, const int* in_sizes, int n_in,
                              void* d_out, int out_size) {
    const float* hidden = (const float*)d_in[0];
    const float* cosb   = (const float*)d_in[1];
    const float* sinb   = (const float*)d_in[2];
    const float* W_rkv  = (const float*)d_in[3];
    const float* W_o    = (const float*)d_in[4];
    const float* tdec   = (const float*)d_in[5];
    const float* tfirst = (const float*)d_in[6];
    const float* tmix   = (const float*)d_in[7];
    float* out = (float*)d_out;

    __half *A2, *B2rkv, *B2o, *rkv;
    cudaGetSymbolAddress((void**)&A2,    g_A2);
    cudaGetSymbolAddress((void**)&B2rkv, g_B2rkv);
    cudaGetSymbolAddress((void**)&B2o,   g_B2o);
    cudaGetSymbolAddress((void**)&rkv,   g_rkv);

    cudaFuncSetAttribute(gemm_hmma<__half>,
                         cudaFuncAttributeMaxDynamicSharedMemorySize, SMEM_DYN);
    cudaFuncSetAttribute(gemm_hmma<float>,
                         cudaFuncAttributeMaxDynamicSharedMemorySize, SMEM_DYN);

    // (1) scalar decay factor
    prep_kernel<<<1, 256>>>(tdec);
    // (2) token mix -> fp16
    mix_split_kernel<<<(M_ * HID_ / 4 + 255) / 256, 256>>>(hidden, tmix);
    // (3) W_rkv -> fp16
    wsplit_kernel<<<(N1_ * HID_ / 4 + 255) / 256, 256>>>(W_rkv, B2rkv, N1_);
    // (4) GEMM1: rkv = mixed @ W_rkv^T (fp16 out)
    gemm_hmma<__half><<<dim3(N1_ / BN_T, M_ / BM_T), 128, SMEM_DYN>>>(
        A2, B2rkv, rkv, N1_);
    // (5) W_o -> fp16
    wsplit_kernel<<<(N2_ * HID_ / 4 + 255) / 256, 256>>>(W_o, B2o, N2_);
    // (6) pass 1: chunk totals (k/v only)
    scanA_kernel<<<(B_ * 64 * HID_) / 256, 256>>>(cosb, sinb);
    // (7) chunk-carry combine
    scanB_kernel<<<(B_ * HID_ + 255) / 256, 256>>>();
    // (8) pass 2: recompute + finalize + gate -> fp16
    scanC_kernel<<<(B_ * 64 * HID_) / 256, 256>>>(cosb, sinb, tfirst);
    // (9) GEMM2: out = att @ W_o^T (fp32 out)
    gemm_hmma<float><<<dim3(N2_ / BN_T, M_ / BM_T), 128, SMEM_DYN>>>(
        A2, B2o, out, N2_);
}